// round 5
// baseline (speedup 1.0000x reference)
#include <cuda_runtime.h>
#include <cuda_bf16.h>
#include <math.h>

#define B_    2
#define S_    2048
#define HID_  768
#define NH_   12
#define HD_   64
#define M_    (B_ * S_)          // 4096 rows
#define WHALF 64                 // WINDOW/2

// Scratch (device globals: no allocations allowed). 16B-aligned for float4.
__device__ __align__(16) float g_v[M_ * HID_];      // q pre-RoPE  == v
__device__ __align__(16) float g_qrot[M_ * HID_];   // q post-RoPE == k
__device__ __align__(16) float g_attn[M_ * HID_];   // attention output

// ---------------------------------------------------------------------------
// 128x128x16 fp32 GEMM. C[m,n] = sum_k A[m,k] * W[n,k].
// 256 threads (16x16). Thread owns rows m0 + ty*8 + i and cols n0 + tx*8 + j
// (both contiguous -> all smem traffic is LDS.128, all gmem stores STG.128).
// RoPE pairing (d, d+32) recovered via __shfl_xor lane^4 in the epilogue.
// Double-buffered smem, one barrier per 16-wide K-step.
// MODE 0: A = Ain (hidden), epilogue = fused RoPE -> g_v, g_qrot.
// MODE 1: A = g_attn (device symbol), epilogue = store to `out`.
// ---------------------------------------------------------------------------
template<int MODE>
__global__ __launch_bounds__(256)
void gemm128(const float* __restrict__ Ain, const float* __restrict__ W,
             float* __restrict__ out) {
    const float* __restrict__ A = (MODE == 0) ? Ain : (const float*)g_attn;

    __shared__ float As[2][16][128];
    __shared__ float Ws[2][16][128];

    const int n0 = blockIdx.x * 128;
    const int m0 = blockIdx.y * 128;
    const int tid = threadIdx.x;
    const int tx = tid & 15, ty = tid >> 4;
    const int lr = tid & 127;          // load row within tile
    const int lk = (tid >> 7) * 8;     // k sub-offset: 0 or 8
    const float* aptr = A + (size_t)(m0 + lr) * HID_ + lk;
    const float* wptr = W + (size_t)(n0 + lr) * HID_ + lk;

    // prologue: load tile 0
    float4 a0 = *(const float4*)(aptr);
    float4 a1 = *(const float4*)(aptr + 4);
    float4 w0 = *(const float4*)(wptr);
    float4 w1 = *(const float4*)(wptr + 4);
    {
        const float av[8] = {a0.x,a0.y,a0.z,a0.w,a1.x,a1.y,a1.z,a1.w};
        const float wv[8] = {w0.x,w0.y,w0.z,w0.w,w1.x,w1.y,w1.z,w1.w};
        #pragma unroll
        for (int c = 0; c < 8; c++) {
            As[0][lk + c][lr] = av[c];
            Ws[0][lk + c][lr] = wv[c];
        }
    }
    __syncthreads();

    float acc[8][8] = {};
    int buf = 0;
    for (int k0 = 0; k0 < HID_; k0 += 16) {
        const bool more = (k0 + 16) < HID_;
        if (more) {
            const float* ap = aptr + k0 + 16;
            const float* wp = wptr + k0 + 16;
            a0 = *(const float4*)(ap);
            a1 = *(const float4*)(ap + 4);
            w0 = *(const float4*)(wp);
            w1 = *(const float4*)(wp + 4);
        }
        #pragma unroll
        for (int kk = 0; kk < 16; kk++) {
            float a[8], b[8];
            *(float4*)&a[0] = *(const float4*)&As[buf][kk][ty * 8];
            *(float4*)&a[4] = *(const float4*)&As[buf][kk][ty * 8 + 4];
            *(float4*)&b[0] = *(const float4*)&Ws[buf][kk][tx * 8];
            *(float4*)&b[4] = *(const float4*)&Ws[buf][kk][tx * 8 + 4];
            #pragma unroll
            for (int i = 0; i < 8; i++)
                #pragma unroll
                for (int j = 0; j < 8; j++) acc[i][j] += a[i] * b[j];
        }
        if (more) {
            const float av[8] = {a0.x,a0.y,a0.z,a0.w,a1.x,a1.y,a1.z,a1.w};
            const float wv[8] = {w0.x,w0.y,w0.z,w0.w,w1.x,w1.y,w1.z,w1.w};
            const int nb = buf ^ 1;
            #pragma unroll
            for (int c = 0; c < 8; c++) {
                As[nb][lk + c][lr] = av[c];
                Ws[nb][lk + c][lr] = wv[c];
            }
            __syncthreads();
            buf = nb;
        }
    }

    const int baseCol = n0 + tx * 8;
    if (MODE == 0) {
        // Fused RoPE. Column c pairs with c^32 -> partner lane = lane^4
        // (columns advance 8 per lane). Both lanes of a pair share d = c&31,
        // hence the same (sin, cos).
        #pragma unroll
        for (int i = 0; i < 8; i++) {
            const int m = m0 + ty * 8 + i;
            const float pos = (float)(m & (S_ - 1));
            float vbuf[8], rbuf[8];
            #pragma unroll
            for (int j = 0; j < 8; j++) {
                const int c = baseCol + j;
                const int d = c & 31;
                const bool lo = (c & 32) == 0;
                const float inv = exp2f((float)d * -0.41524101186920654f);
                float sn, cs;
                sincosf(pos * inv, &sn, &cs);
                const float mine  = acc[i][j];
                const float other = __shfl_xor_sync(0xffffffffu, mine, 4);
                const float qlo = lo ? mine : other;
                const float qhi = lo ? other : mine;
                vbuf[j] = mine;
                rbuf[j] = lo ? (qlo * cs - qhi * sn) : (qhi * cs + qlo * sn);
            }
            float* vp = &g_v[(size_t)m * HID_ + baseCol];
            float* rp = &g_qrot[(size_t)m * HID_ + baseCol];
            *(float4*)(vp)     = *(float4*)&vbuf[0];
            *(float4*)(vp + 4) = *(float4*)&vbuf[4];
            *(float4*)(rp)     = *(float4*)&rbuf[0];
            *(float4*)(rp + 4) = *(float4*)&rbuf[4];
        }
    } else {
        #pragma unroll
        for (int i = 0; i < 8; i++) {
            const int m = m0 + ty * 8 + i;
            float* op = &out[(size_t)m * HID_ + baseCol];
            *(float4*)(op)     = *(float4*)&acc[i][0];
            *(float4*)(op + 4) = *(float4*)&acc[i][4];
        }
    }
}

// ---------------------------------------------------------------------------
// Sliding-window attention (unchanged — isolate the GEMM change).
// One block = 64 queries of one (b,h); keys = 3 chunks of 64.
// ---------------------------------------------------------------------------
#define ATTN_SMEM_FLOATS (64 * 65 * 2 + 64 * 193)

__global__ __launch_bounds__(256)
void attn_kernel() {
    extern __shared__ float sm[];
    float* Qs  = sm;                 // [64][65]
    float* KVs = Qs + 64 * 65;       // [64][65]
    float* Ps  = KVs + 64 * 65;      // [64][193]

    const int t0 = blockIdx.x * 64;
    const int bh = blockIdx.y;
    const int b = bh / NH_, h = bh % NH_;
    const int tid = threadIdx.x;
    const int tx = tid & 15, ty = tid >> 4;

    const float* qbase = g_qrot + b * (S_ * HID_) + h * HD_;
    const float* vbase = g_v    + b * (S_ * HID_) + h * HD_;

    for (int idx = tid; idx < 64 * 64; idx += 256) {
        int r = idx >> 6, c = idx & 63;
        Qs[r * 65 + c] = qbase[(t0 + r) * HID_ + c];
    }

    for (int kc = 0; kc < 3; kc++) {
        int s0 = t0 - 64 + kc * 64;
        __syncthreads();
        for (int idx = tid; idx < 64 * 64; idx += 256) {
            int r = idx >> 6, c = idx & 63;
            int s = s0 + r;
            KVs[r * 65 + c] = ((unsigned)s < (unsigned)S_)
                              ? qbase[s * HID_ + c] : 0.0f;
        }
        __syncthreads();

        float acc[4][4] = {};
        #pragma unroll
        for (int dd = 0; dd < 64; dd++) {
            float a[4], bb[4];
            #pragma unroll
            for (int i = 0; i < 4; i++) a[i] = Qs[(ty + 16 * i) * 65 + dd];
            #pragma unroll
            for (int j = 0; j < 4; j++) bb[j] = KVs[(tx + 16 * j) * 65 + dd];
            #pragma unroll
            for (int i = 0; i < 4; i++)
                #pragma unroll
                for (int j = 0; j < 4; j++) acc[i][j] += a[i] * bb[j];
        }
        #pragma unroll
        for (int i = 0; i < 4; i++) {
            int qi = ty + 16 * i, t = t0 + qi;
            #pragma unroll
            for (int j = 0; j < 4; j++) {
                int kj = tx + 16 * j, s = s0 + kj;
                int dist = t - s; if (dist < 0) dist = -dist;
                bool valid = ((unsigned)s < (unsigned)S_) && (dist <= WHALF);
                Ps[qi * 193 + kc * 64 + kj] = valid ? acc[i][j] * 0.125f : -1e30f;
            }
        }
    }
    __syncthreads();

    const int warp = tid >> 5, lane = tid & 31;
    for (int r = warp; r < 64; r += 8) {
        float mx = -1e30f;
        for (int c = lane; c < 192; c += 32) mx = fmaxf(mx, Ps[r * 193 + c]);
        #pragma unroll
        for (int off = 16; off; off >>= 1)
            mx = fmaxf(mx, __shfl_xor_sync(0xffffffffu, mx, off));
        float sum = 0.0f;
        for (int c = lane; c < 192; c += 32) {
            float e = __expf(Ps[r * 193 + c] - mx);
            Ps[r * 193 + c] = e;
            sum += e;
        }
        #pragma unroll
        for (int off = 16; off; off >>= 1)
            sum += __shfl_xor_sync(0xffffffffu, sum, off);
        float inv = 1.0f / sum;
        for (int c = lane; c < 192; c += 32) Ps[r * 193 + c] *= inv;
    }
    __syncthreads();

    float o[4][4] = {};
    for (int kc = 0; kc < 3; kc++) {
        int s0 = t0 - 64 + kc * 64;
        for (int idx = tid; idx < 64 * 64; idx += 256) {
            int r = idx >> 6, c = idx & 63;
            int s = s0 + r;
            KVs[r * 65 + c] = ((unsigned)s < (unsigned)S_)
                              ? vbase[s * HID_ + c] : 0.0f;
        }
        __syncthreads();
        #pragma unroll
        for (int kk = 0; kk < 64; kk++) {
            float a[4], bb[4];
            #pragma unroll
            for (int i = 0; i < 4; i++)
                a[i] = Ps[(ty + 16 * i) * 193 + kc * 64 + kk];
            #pragma unroll
            for (int j = 0; j < 4; j++)
                bb[j] = KVs[kk * 65 + tx + 16 * j];
            #pragma unroll
            for (int i = 0; i < 4; i++)
                #pragma unroll
                for (int j = 0; j < 4; j++) o[i][j] += a[i] * bb[j];
        }
        __syncthreads();
    }

    float* obase = g_attn + b * (S_ * HID_) + h * HD_;
    #pragma unroll
    for (int i = 0; i < 4; i++)
        #pragma unroll
        for (int j = 0; j < 4; j++)
            obase[(t0 + ty + 16 * i) * HID_ + tx + 16 * j] = o[i][j];
}

// ---------------------------------------------------------------------------
extern "C" void kernel_launch(void* const* d_in, const int* in_sizes, int n_in,
                              void* d_out, int out_size) {
    const float* hidden = (const float*)d_in[0];   // [B,S,HID]
    const float* Wq     = (const float*)d_in[1];   // [HID,HID]
    const float* Wo     = (const float*)d_in[2];   // [HID,HID]
    float* out = (float*)d_out;

    (void)in_sizes; (void)n_in; (void)out_size;

    const size_t attn_smem = ATTN_SMEM_FLOATS * sizeof(float);  // ~82.7 KB
    cudaFuncSetAttribute(attn_kernel,
                         cudaFuncAttributeMaxDynamicSharedMemorySize,
                         (int)attn_smem);

    dim3 gemm_grid(HID_ / 128, M_ / 128);   // (6, 32)
    gemm128<0><<<gemm_grid, 256>>>(hidden, Wq, nullptr);

    dim3 attn_grid(S_ / 64, B_ * NH_);      // (32, 24)
    attn_kernel<<<attn_grid, 256, attn_smem>>>();

    gemm128<1><<<gemm_grid, 256>>>(nullptr, Wo, out);  // A = g_attn
}

// round 8
// speedup vs baseline: 1.5481x; 1.5481x over previous
#include <cuda_runtime.h>
#include <cuda_bf16.h>
#include <math.h>
#include <stdint.h>

#define B_    2
#define S_    2048
#define HID_  768
#define NH_   12
#define HD_   64
#define M_    (B_ * S_)          // 4096 rows
#define WHALF 64                 // WINDOW/2

// ---------------- device scratch (no allocations allowed) ------------------
__device__ __align__(16) float g_v[M_ * HID_];      // q pre-RoPE  == v
__device__ __align__(16) float g_qrot[M_ * HID_];   // q post-RoPE == k
__device__ __align__(16) float g_attn[M_ * HID_];   // attention output

// bf16 split operands
__device__ __align__(16) __nv_bfloat16 gAh[M_ * HID_];
__device__ __align__(16) __nv_bfloat16 gAl[M_ * HID_];
__device__ __align__(16) __nv_bfloat16 gW1h[HID_ * HID_];
__device__ __align__(16) __nv_bfloat16 gW1l[HID_ * HID_];
__device__ __align__(16) __nv_bfloat16 gW2h[HID_ * HID_];
__device__ __align__(16) __nv_bfloat16 gW2l[HID_ * HID_];

// ---------------- PTX helpers (baseline ISA: ldmatrix + mma.sync) ----------
__device__ __forceinline__ uint32_t smem_u32(const void* p) {
    uint32_t a;
    asm("{ .reg .u64 t; cvta.to.shared.u64 t, %1; cvt.u32.u64 %0, t; }"
        : "=r"(a) : "l"(p));
    return a;
}
__device__ __forceinline__ void ldmx4(uint32_t r[4], uint32_t addr) {
    asm volatile("ldmatrix.sync.aligned.m8n8.x4.shared.b16 {%0,%1,%2,%3}, [%4];"
                 : "=r"(r[0]), "=r"(r[1]), "=r"(r[2]), "=r"(r[3]) : "r"(addr));
}
__device__ __forceinline__ void ldmx2(uint32_t r[2], uint32_t addr) {
    asm volatile("ldmatrix.sync.aligned.m8n8.x2.shared.b16 {%0,%1}, [%2];"
                 : "=r"(r[0]), "=r"(r[1]) : "r"(addr));
}
__device__ __forceinline__ void mma_bf16(float c[4], const uint32_t a[4],
                                         const uint32_t b[2]) {
    asm volatile(
        "mma.sync.aligned.m16n8k16.row.col.f32.bf16.bf16.f32 "
        "{%0,%1,%2,%3}, {%4,%5,%6,%7}, {%8,%9}, {%0,%1,%2,%3};"
        : "+f"(c[0]), "+f"(c[1]), "+f"(c[2]), "+f"(c[3])
        : "r"(a[0]), "r"(a[1]), "r"(a[2]), "r"(a[3]), "r"(b[0]), "r"(b[1]));
}
#define SWZ128(off) ((off) ^ (((off) >> 3) & 0x70))

// ---------------------------------------------------------------------------
// split convert: fp32 -> bf16 hi + bf16 lo residual.
// ALL device symbols selected in DEVICE code via template params — never
// passed as kernel arguments from host (host sees only shadow addresses).
// SRC: 0 = srcin param, 1 = g_attn.   DST: 0 = gA*, 1 = gW1*, 2 = gW2*.
// ---------------------------------------------------------------------------
template<int SRC, int DST>
__global__ __launch_bounds__(256)
void split_bf16(const float* __restrict__ srcin, int n) {
    const float* __restrict__ src = (SRC == 0) ? srcin : (const float*)g_attn;
    __nv_bfloat16* __restrict__ hi = (DST == 0) ? gAh : (DST == 1) ? gW1h : gW2h;
    __nv_bfloat16* __restrict__ lo = (DST == 0) ? gAl : (DST == 1) ? gW1l : gW2l;
    int i = (blockIdx.x * 256 + threadIdx.x) * 4;
    if (i >= n) return;
    float4 v = *(const float4*)(src + i);
    __nv_bfloat16 h0 = __float2bfloat16(v.x);
    __nv_bfloat16 h1 = __float2bfloat16(v.y);
    __nv_bfloat16 h2 = __float2bfloat16(v.z);
    __nv_bfloat16 h3 = __float2bfloat16(v.w);
    __nv_bfloat16 l0 = __float2bfloat16(v.x - __bfloat162float(h0));
    __nv_bfloat16 l1 = __float2bfloat16(v.y - __bfloat162float(h1));
    __nv_bfloat16 l2 = __float2bfloat16(v.z - __bfloat162float(h2));
    __nv_bfloat16 l3 = __float2bfloat16(v.w - __bfloat162float(h3));
    *(__nv_bfloat162*)(hi + i)     = __nv_bfloat162(h0, h1);
    *(__nv_bfloat162*)(hi + i + 2) = __nv_bfloat162(h2, h3);
    *(__nv_bfloat162*)(lo + i)     = __nv_bfloat162(l0, l1);
    *(__nv_bfloat162*)(lo + i + 2) = __nv_bfloat162(l2, l3);
}

// ---------------------------------------------------------------------------
// HMMA GEMM: C[m,n] = sum_k A[m,k]*W[n,k], bf16 split (3 mma terms).
// CTA tile 128x128, K chunks of 64 (SW128 smem). 8 warps 2(m)x4(n),
// warp tile 64x32 = 4 m-tiles x 4 n-tiles of m16n8k16.
// Epilogue stages C in smem -> coalesced fp32 stores (+ fused RoPE, MODE 0).
// ---------------------------------------------------------------------------
#define STAGE_PITCH 132
#define GT_SMEM (128 * STAGE_PITCH * 4 > 1024 + 4 * 16384 ? \
                 128 * STAGE_PITCH * 4 : 1024 + 4 * 16384)

template<int MODE>
__global__ __launch_bounds__(256)
void gemm_mma(float* __restrict__ out) {
    extern __shared__ __align__(1024) char sm[];
    const uint32_t smb = smem_u32(sm);
    const uint32_t uAh = smb + 1024;
    const uint32_t uAl = uAh + 16384;
    const uint32_t uWh = uAl + 16384;
    const uint32_t uWl = uWh + 16384;
    char* sAh = sm + 1024;
    char* sAl = sm + 1024 + 16384;
    char* sWh = sm + 1024 + 2 * 16384;
    char* sWl = sm + 1024 + 3 * 16384;

    const int n0 = blockIdx.x * 128;
    const int m0 = blockIdx.y * 128;
    const int tid = threadIdx.x;
    const int wid = tid >> 5, lane = tid & 31;
    const int wm = (wid >> 2) * 64;   // warp m offset (0 / 64)
    const int wn = (wid & 3) * 32;    // warp n offset (0/32/64/96)

    const __nv_bfloat16* __restrict__ Bh = (MODE == 0) ? gW1h : gW2h;
    const __nv_bfloat16* __restrict__ Bl = (MODE == 0) ? gW1l : gW2l;

    float acc[4][4][4] = {};   // [mt][nt][frag]

    const int arow = lane & 15;
    const int ahalf = (lane >> 4) << 4;
    const int brow = lane & 7;
    const int bhalf = ((lane >> 3) & 1) << 4;

    for (int c = 0; c < 12; c++) {
        const int k0 = c * 64;
        #pragma unroll
        for (int t = 0; t < 4; t++) {
            const int idx = tid + t * 256;       // 0..1023
            const int row = idx >> 3;
            const int seg = idx & 7;
            const uint32_t d = SWZ128(row * 128 + seg * 16);
            const size_t ga = (size_t)(m0 + row) * HID_ + k0 + seg * 8;
            const size_t gw = (size_t)(n0 + row) * HID_ + k0 + seg * 8;
            *(int4*)(sAh + d) = *(const int4*)(gAh + ga);
            *(int4*)(sAl + d) = *(const int4*)(gAl + ga);
            *(int4*)(sWh + d) = *(const int4*)(Bh + gw);
            *(int4*)(sWl + d) = *(const int4*)(Bl + gw);
        }
        __syncthreads();

        #pragma unroll
        for (int ks = 0; ks < 4; ks++) {
            const int kb = ks * 32;
            uint32_t ah[4][4], bh2[4][2], bl2[4][2];
            #pragma unroll
            for (int mt = 0; mt < 4; mt++) {
                const int r = wm + mt * 16 + arow;
                ldmx4(ah[mt], uAh + SWZ128(r * 128 + kb + ahalf));
            }
            #pragma unroll
            for (int nt = 0; nt < 4; nt++) {
                const int r = wn + nt * 8 + brow;
                const uint32_t off = SWZ128(r * 128 + kb + bhalf);
                ldmx2(bh2[nt], uWh + off);
                ldmx2(bl2[nt], uWl + off);
            }
            #pragma unroll
            for (int mt = 0; mt < 4; mt++)
                #pragma unroll
                for (int nt = 0; nt < 4; nt++) {
                    mma_bf16(acc[mt][nt], ah[mt], bh2[nt]);
                    mma_bf16(acc[mt][nt], ah[mt], bl2[nt]);
                }
            uint32_t al[4];
            #pragma unroll
            for (int mt = 0; mt < 4; mt++) {
                const int r = wm + mt * 16 + arow;
                ldmx4(al, uAl + SWZ128(r * 128 + kb + ahalf));
                #pragma unroll
                for (int nt = 0; nt < 4; nt++)
                    mma_bf16(acc[mt][nt], al, bh2[nt]);
            }
        }
        __syncthreads();
    }

    // ---- epilogue: stage C into smem fp32, then coalesced processing ----
    float* stage = (float*)sm;   // [128][STAGE_PITCH]
    #pragma unroll
    for (int mt = 0; mt < 4; mt++)
        #pragma unroll
        for (int nt = 0; nt < 4; nt++) {
            const int r = wm + mt * 16 + (lane >> 2);
            const int cc = wn + nt * 8 + 2 * (lane & 3);
            *(float2*)&stage[r * STAGE_PITCH + cc] =
                make_float2(acc[mt][nt][0], acc[mt][nt][1]);
            *(float2*)&stage[(r + 8) * STAGE_PITCH + cc] =
                make_float2(acc[mt][nt][2], acc[mt][nt][3]);
        }
    __syncthreads();

    const int row = tid >> 1;            // 0..127
    const int hh  = tid & 1;             // which 64-col head half
    const int m = m0 + row;
    const float* srow = &stage[row * STAGE_PITCH + hh * 64];
    if (MODE == 0) {
        const float pos = (float)(m & (S_ - 1));
        float vb[64], rb[64];
        #pragma unroll
        for (int d = 0; d < 32; d++) {
            const float qlo = srow[d];
            const float qhi = srow[d + 32];
            const float inv = exp2f((float)d * -0.41524101186920654f);
            float sn, cs;
            sincosf(pos * inv, &sn, &cs);
            vb[d] = qlo;      vb[d + 32] = qhi;
            rb[d] = qlo * cs - qhi * sn;
            rb[d + 32] = qhi * cs + qlo * sn;
        }
        float* vp = &g_v[(size_t)m * HID_ + n0 + hh * 64];
        float* rp = &g_qrot[(size_t)m * HID_ + n0 + hh * 64];
        #pragma unroll
        for (int q = 0; q < 16; q++) {
            *(float4*)(vp + q * 4) = *(float4*)&vb[q * 4];
            *(float4*)(rp + q * 4) = *(float4*)&rb[q * 4];
        }
    } else {
        float* op = &out[(size_t)m * HID_ + n0 + hh * 64];
        #pragma unroll
        for (int q = 0; q < 16; q++) {
            float4 f = make_float4(srow[q * 4], srow[q * 4 + 1],
                                   srow[q * 4 + 2], srow[q * 4 + 3]);
            *(float4*)(op + q * 4) = f;
        }
    }
}

// ---------------------------------------------------------------------------
// Sliding-window attention (unchanged, fp32).
// ---------------------------------------------------------------------------
#define ATTN_SMEM_FLOATS (64 * 65 * 2 + 64 * 193)

__global__ __launch_bounds__(256)
void attn_kernel() {
    extern __shared__ float smf[];
    float* Qs  = smf;
    float* KVs = Qs + 64 * 65;
    float* Ps  = KVs + 64 * 65;

    const int t0 = blockIdx.x * 64;
    const int bh = blockIdx.y;
    const int b = bh / NH_, h = bh % NH_;
    const int tid = threadIdx.x;
    const int tx = tid & 15, ty = tid >> 4;

    const float* qbase = g_qrot + b * (S_ * HID_) + h * HD_;
    const float* vbase = g_v    + b * (S_ * HID_) + h * HD_;

    for (int idx = tid; idx < 64 * 64; idx += 256) {
        int r = idx >> 6, c = idx & 63;
        Qs[r * 65 + c] = qbase[(t0 + r) * HID_ + c];
    }

    for (int kc = 0; kc < 3; kc++) {
        int s0 = t0 - 64 + kc * 64;
        __syncthreads();
        for (int idx = tid; idx < 64 * 64; idx += 256) {
            int r = idx >> 6, c = idx & 63;
            int s = s0 + r;
            KVs[r * 65 + c] = ((unsigned)s < (unsigned)S_)
                              ? qbase[s * HID_ + c] : 0.0f;
        }
        __syncthreads();

        float acc[4][4] = {};
        #pragma unroll
        for (int dd = 0; dd < 64; dd++) {
            float a[4], bb[4];
            #pragma unroll
            for (int i = 0; i < 4; i++) a[i] = Qs[(ty + 16 * i) * 65 + dd];
            #pragma unroll
            for (int j = 0; j < 4; j++) bb[j] = KVs[(tx + 16 * j) * 65 + dd];
            #pragma unroll
            for (int i = 0; i < 4; i++)
                #pragma unroll
                for (int j = 0; j < 4; j++) acc[i][j] += a[i] * bb[j];
        }
        #pragma unroll
        for (int i = 0; i < 4; i++) {
            int qi = ty + 16 * i, t = t0 + qi;
            #pragma unroll
            for (int j = 0; j < 4; j++) {
                int kj = tx + 16 * j, s = s0 + kj;
                int dist = t - s; if (dist < 0) dist = -dist;
                bool valid = ((unsigned)s < (unsigned)S_) && (dist <= WHALF);
                Ps[qi * 193 + kc * 64 + kj] = valid ? acc[i][j] * 0.125f : -1e30f;
            }
        }
    }
    __syncthreads();

    const int warp = tid >> 5, lane = tid & 31;
    for (int r = warp; r < 64; r += 8) {
        float mx = -1e30f;
        for (int c = lane; c < 192; c += 32) mx = fmaxf(mx, Ps[r * 193 + c]);
        #pragma unroll
        for (int off = 16; off; off >>= 1)
            mx = fmaxf(mx, __shfl_xor_sync(0xffffffffu, mx, off));
        float sum = 0.0f;
        for (int c = lane; c < 192; c += 32) {
            float e = __expf(Ps[r * 193 + c] - mx);
            Ps[r * 193 + c] = e;
            sum += e;
        }
        #pragma unroll
        for (int off = 16; off; off >>= 1)
            sum += __shfl_xor_sync(0xffffffffu, sum, off);
        float inv = 1.0f / sum;
        for (int c = lane; c < 192; c += 32) Ps[r * 193 + c] *= inv;
    }
    __syncthreads();

    float o[4][4] = {};
    for (int kc = 0; kc < 3; kc++) {
        int s0 = t0 - 64 + kc * 64;
        for (int idx = tid; idx < 64 * 64; idx += 256) {
            int r = idx >> 6, c = idx & 63;
            int s = s0 + r;
            KVs[r * 65 + c] = ((unsigned)s < (unsigned)S_)
                              ? vbase[s * HID_ + c] : 0.0f;
        }
        __syncthreads();
        #pragma unroll
        for (int kk = 0; kk < 64; kk++) {
            float a[4], bb[4];
            #pragma unroll
            for (int i = 0; i < 4; i++)
                a[i] = Ps[(ty + 16 * i) * 193 + kc * 64 + kk];
            #pragma unroll
            for (int j = 0; j < 4; j++)
                bb[j] = KVs[kk * 65 + tx + 16 * j];
            #pragma unroll
            for (int i = 0; i < 4; i++)
                #pragma unroll
                for (int j = 0; j < 4; j++) o[i][j] += a[i] * bb[j];
        }
        __syncthreads();
    }

    float* obase = g_attn + b * (S_ * HID_) + h * HD_;
    #pragma unroll
    for (int i = 0; i < 4; i++)
        #pragma unroll
        for (int j = 0; j < 4; j++)
            obase[(t0 + ty + 16 * i) * HID_ + tx + 16 * j] = o[i][j];
}

// ---------------------------------------------------------------------------
extern "C" void kernel_launch(void* const* d_in, const int* in_sizes, int n_in,
                              void* d_out, int out_size) {
    const float* hidden = (const float*)d_in[0];   // [B,S,HID]
    const float* Wq     = (const float*)d_in[1];   // [HID,HID]
    const float* Wo     = (const float*)d_in[2];   // [HID,HID]
    float* out = (float*)d_out;
    (void)in_sizes; (void)n_in; (void)out_size;

    const size_t attn_smem = ATTN_SMEM_FLOATS * sizeof(float);
    cudaFuncSetAttribute(attn_kernel,
                         cudaFuncAttributeMaxDynamicSharedMemorySize,
                         (int)attn_smem);
    cudaFuncSetAttribute(gemm_mma<0>,
                         cudaFuncAttributeMaxDynamicSharedMemorySize, GT_SMEM);
    cudaFuncSetAttribute(gemm_mma<1>,
                         cudaFuncAttributeMaxDynamicSharedMemorySize, GT_SMEM);

    // bf16 split converts — device buffers selected inside the kernels
    split_bf16<0, 0><<<(M_ * HID_ / 4 + 255) / 256, 256>>>(hidden, M_ * HID_);
    split_bf16<0, 1><<<(HID_ * HID_ / 4 + 255) / 256, 256>>>(Wq, HID_ * HID_);
    split_bf16<0, 2><<<(HID_ * HID_ / 4 + 255) / 256, 256>>>(Wo, HID_ * HID_);

    dim3 gemm_grid(HID_ / 128, M_ / 128);   // (6, 32)
    gemm_mma<0><<<gemm_grid, 256, GT_SMEM>>>(nullptr);

    dim3 attn_grid(S_ / 64, B_ * NH_);      // (32, 24)
    attn_kernel<<<attn_grid, 256, attn_smem>>>();

    split_bf16<1, 0><<<(M_ * HID_ / 4 + 255) / 256, 256>>>(nullptr, M_ * HID_);
    gemm_mma<1><<<gemm_grid, 256, GT_SMEM>>>(out);
}

// round 9
// speedup vs baseline: 1.7838x; 1.1523x over previous
#include <cuda_runtime.h>
#include <cuda_bf16.h>
#include <math.h>
#include <stdint.h>

#define B_    2
#define S_    2048
#define HID_  768
#define NH_   12
#define HD_   64
#define M_    (B_ * S_)          // 4096 rows
#define WHALF 64                 // WINDOW/2

// ---------------- device scratch (no allocations allowed) ------------------
__device__ __align__(16) float g_v[M_ * HID_];      // q pre-RoPE  == v
__device__ __align__(16) float g_qrot[M_ * HID_];   // q post-RoPE == k
__device__ __align__(16) float g_attn[M_ * HID_];   // attention output

// bf16 split operands
__device__ __align__(16) __nv_bfloat16 gAh[M_ * HID_];
__device__ __align__(16) __nv_bfloat16 gAl[M_ * HID_];
__device__ __align__(16) __nv_bfloat16 gW1h[HID_ * HID_];
__device__ __align__(16) __nv_bfloat16 gW1l[HID_ * HID_];
__device__ __align__(16) __nv_bfloat16 gW2h[HID_ * HID_];
__device__ __align__(16) __nv_bfloat16 gW2l[HID_ * HID_];

// ---------------- PTX helpers (baseline ISA only) --------------------------
__device__ __forceinline__ uint32_t smem_u32(const void* p) {
    uint32_t a;
    asm("{ .reg .u64 t; cvta.to.shared.u64 t, %1; cvt.u32.u64 %0, t; }"
        : "=r"(a) : "l"(p));
    return a;
}
__device__ __forceinline__ void ldmx4(uint32_t r[4], uint32_t addr) {
    asm volatile("ldmatrix.sync.aligned.m8n8.x4.shared.b16 {%0,%1,%2,%3}, [%4];"
                 : "=r"(r[0]), "=r"(r[1]), "=r"(r[2]), "=r"(r[3]) : "r"(addr));
}
__device__ __forceinline__ void ldmx2(uint32_t r[2], uint32_t addr) {
    asm volatile("ldmatrix.sync.aligned.m8n8.x2.shared.b16 {%0,%1}, [%2];"
                 : "=r"(r[0]), "=r"(r[1]) : "r"(addr));
}
__device__ __forceinline__ void mma_bf16(float c[4], const uint32_t a[4],
                                         const uint32_t b[2]) {
    asm volatile(
        "mma.sync.aligned.m16n8k16.row.col.f32.bf16.bf16.f32 "
        "{%0,%1,%2,%3}, {%4,%5,%6,%7}, {%8,%9}, {%0,%1,%2,%3};"
        : "+f"(c[0]), "+f"(c[1]), "+f"(c[2]), "+f"(c[3])
        : "r"(a[0]), "r"(a[1]), "r"(a[2]), "r"(a[3]), "r"(b[0]), "r"(b[1]));
}
__device__ __forceinline__ void cp16(uint32_t dst, const void* src) {
    asm volatile("cp.async.cg.shared.global [%0], [%1], 16;"
                 :: "r"(dst), "l"(src));
}
#define CP_COMMIT() asm volatile("cp.async.commit_group;" ::: "memory")
#define CP_WAIT1()  asm volatile("cp.async.wait_group 1;" ::: "memory")

// 64B-row swizzle: col16 bits[5:4] ^= row bits[2:1] (off bits [8:7]).
// Conflict-free for ldmatrix 8-lane phases on 64B rows.
#define SWZ64(off) ((off) ^ (((off) >> 3) & 0x30))

// ---------------------------------------------------------------------------
// split convert: fp32 -> bf16 hi + bf16 lo residual. Device symbols selected
// in device code only (template params), never passed from host.
// SRC: 0 = srcin param, 1 = g_attn.   DST: 0 = gA*, 1 = gW1*, 2 = gW2*.
// ---------------------------------------------------------------------------
template<int SRC, int DST>
__global__ __launch_bounds__(256)
void split_bf16(const float* __restrict__ srcin, int n) {
    const float* __restrict__ src = (SRC == 0) ? srcin : (const float*)g_attn;
    __nv_bfloat16* __restrict__ hi = (DST == 0) ? gAh : (DST == 1) ? gW1h : gW2h;
    __nv_bfloat16* __restrict__ lo = (DST == 0) ? gAl : (DST == 1) ? gW1l : gW2l;
    int i = (blockIdx.x * 256 + threadIdx.x) * 4;
    if (i >= n) return;
    float4 v = *(const float4*)(src + i);
    __nv_bfloat16 h0 = __float2bfloat16(v.x);
    __nv_bfloat16 h1 = __float2bfloat16(v.y);
    __nv_bfloat16 h2 = __float2bfloat16(v.z);
    __nv_bfloat16 h3 = __float2bfloat16(v.w);
    __nv_bfloat16 l0 = __float2bfloat16(v.x - __bfloat162float(h0));
    __nv_bfloat16 l1 = __float2bfloat16(v.y - __bfloat162float(h1));
    __nv_bfloat16 l2 = __float2bfloat16(v.z - __bfloat162float(h2));
    __nv_bfloat16 l3 = __float2bfloat16(v.w - __bfloat162float(h3));
    *(__nv_bfloat162*)(hi + i)     = __nv_bfloat162(h0, h1);
    *(__nv_bfloat162*)(hi + i + 2) = __nv_bfloat162(h2, h3);
    *(__nv_bfloat162*)(lo + i)     = __nv_bfloat162(l0, l1);
    *(__nv_bfloat162*)(lo + i + 2) = __nv_bfloat162(l2, l3);
}

// ---------------------------------------------------------------------------
// Pipelined HMMA GEMM: C[m,n] = sum_k A[m,k]*W[n,k], bf16 split (3 terms).
// CTA tile 128x128. K chunks of 32 (64B rows, SWZ64), cp.async double buffer.
// 8 warps 2(m)x4(n), warp tile 64x32. __launch_bounds__(256,2) -> 2 CTA/SM,
// grid 192 fits in ONE wave (296 slots).
// smem: [0,1024) pad, stage b at 1024 + b*32768: Ah,Al,Wh,Wl (8KB each).
// Epilogue staging overlays from offset 0 (needs 67.6KB total).
// ---------------------------------------------------------------------------
#define TILE_B   8192                       // one operand tile (128 x 64B)
#define STAGE_B  (4 * TILE_B)               // 4 tiles per stage
#define STAGE_PITCH 132
#define GT_SMEM (128 * STAGE_PITCH * 4)     // 67584 > 1024 + 2*32768 = 66560
#define NCHUNK (HID_ / 32)                  // 24

template<int MODE>
__global__ __launch_bounds__(256, 2)
void gemm_mma(float* __restrict__ out) {
    extern __shared__ __align__(1024) char sm[];
    const uint32_t smb = smem_u32(sm);

    const int n0 = blockIdx.x * 128;
    const int m0 = blockIdx.y * 128;
    const int tid = threadIdx.x;
    const int wid = tid >> 5, lane = tid & 31;
    const int wm = (wid >> 2) * 64;   // warp m offset (0 / 64)
    const int wn = (wid & 3) * 32;    // warp n offset (0/32/64/96)

    const __nv_bfloat16* __restrict__ Bh = (MODE == 0) ? gW1h : gW2h;
    const __nv_bfloat16* __restrict__ Bl = (MODE == 0) ? gW1l : gW2l;

    // loader indexing: 8KB tile = 512 x 16B segs; 256 thr -> 2 segs/thread/tile
    const int lrow0 = tid >> 2;            // seg set 0: rows 0..63
    const int lseg  = tid & 3;
    // gmem element offsets (row * HID_ + seg*8), k0 added per chunk
    const size_t gA0 = (size_t)(m0 + lrow0) * HID_ + lseg * 8;
    const size_t gA1 = (size_t)(m0 + lrow0 + 64) * HID_ + lseg * 8;
    const size_t gW0 = (size_t)(n0 + lrow0) * HID_ + lseg * 8;
    const size_t gW1v = (size_t)(n0 + lrow0 + 64) * HID_ + lseg * 8;
    const uint32_t so0 = SWZ64((uint32_t)(lrow0 * 64 + lseg * 16));
    const uint32_t so1 = SWZ64((uint32_t)((lrow0 + 64) * 64 + lseg * 16));

    #define LOAD_CHUNK(cc, bufb)                                              \
    {                                                                         \
        const int k0_ = (cc) * 32;                                            \
        const uint32_t s_ = smb + 1024 + (bufb) * STAGE_B;                    \
        cp16(s_ + so0,              gAh + gA0 + k0_);                         \
        cp16(s_ + so1,              gAh + gA1 + k0_);                         \
        cp16(s_ + TILE_B + so0,     gAl + gA0 + k0_);                         \
        cp16(s_ + TILE_B + so1,     gAl + gA1 + k0_);                         \
        cp16(s_ + 2 * TILE_B + so0, Bh + gW0 + k0_);                          \
        cp16(s_ + 2 * TILE_B + so1, Bh + gW1v + k0_);                         \
        cp16(s_ + 3 * TILE_B + so0, Bl + gW0 + k0_);                          \
        cp16(s_ + 3 * TILE_B + so1, Bl + gW1v + k0_);                         \
    }

    float acc[4][4][4] = {};   // [mt][nt][frag]

    const int arow = lane & 15;
    const int ahalf = (lane >> 4) << 4;
    const int brow = lane & 7;
    const int bhalf = ((lane >> 3) & 1) << 4;

    // prologue: prefetch chunks 0 and 1
    LOAD_CHUNK(0, 0); CP_COMMIT();
    LOAD_CHUNK(1, 1); CP_COMMIT();

    for (int c = 0; c < NCHUNK; c++) {
        const int buf = c & 1;
        const uint32_t uAh = smb + 1024 + buf * STAGE_B;
        const uint32_t uAl = uAh + TILE_B;
        const uint32_t uWh = uAh + 2 * TILE_B;
        const uint32_t uWl = uAh + 3 * TILE_B;

        CP_WAIT1();            // chunk c's group complete
        __syncthreads();

        #pragma unroll
        for (int ks = 0; ks < 2; ks++) {
            const int kb = ks * 32;    // byte offset of this k16 step
            uint32_t ah[4][4], bh2[4][2], bl2[4][2];
            #pragma unroll
            for (int mt = 0; mt < 4; mt++) {
                const int r = wm + mt * 16 + arow;
                ldmx4(ah[mt], uAh + SWZ64(r * 64 + kb + ahalf));
            }
            #pragma unroll
            for (int nt = 0; nt < 4; nt++) {
                const int r = wn + nt * 8 + brow;
                const uint32_t off = SWZ64(r * 64 + kb + bhalf);
                ldmx2(bh2[nt], uWh + off);
                ldmx2(bl2[nt], uWl + off);
            }
            #pragma unroll
            for (int mt = 0; mt < 4; mt++)
                #pragma unroll
                for (int nt = 0; nt < 4; nt++) {
                    mma_bf16(acc[mt][nt], ah[mt], bh2[nt]);
                    mma_bf16(acc[mt][nt], ah[mt], bl2[nt]);
                }
            uint32_t al[4];
            #pragma unroll
            for (int mt = 0; mt < 4; mt++) {
                const int r = wm + mt * 16 + arow;
                ldmx4(al, uAl + SWZ64(r * 64 + kb + ahalf));
                #pragma unroll
                for (int nt = 0; nt < 4; nt++)
                    mma_bf16(acc[mt][nt], al, bh2[nt]);
            }
        }
        __syncthreads();       // all warps done reading buf before refill
        if (c + 2 < NCHUNK) LOAD_CHUNK(c + 2, buf);
        CP_COMMIT();           // empty groups keep wait_group accounting
    }
    #undef LOAD_CHUNK

    // ---- epilogue: stage C into smem fp32, then coalesced processing ----
    float* stage = (float*)sm;   // [128][STAGE_PITCH]
    #pragma unroll
    for (int mt = 0; mt < 4; mt++)
        #pragma unroll
        for (int nt = 0; nt < 4; nt++) {
            const int r = wm + mt * 16 + (lane >> 2);
            const int cc = wn + nt * 8 + 2 * (lane & 3);
            *(float2*)&stage[r * STAGE_PITCH + cc] =
                make_float2(acc[mt][nt][0], acc[mt][nt][1]);
            *(float2*)&stage[(r + 8) * STAGE_PITCH + cc] =
                make_float2(acc[mt][nt][2], acc[mt][nt][3]);
        }
    __syncthreads();

    const int row = tid >> 1;            // 0..127
    const int hh  = tid & 1;             // which 64-col head half
    const int m = m0 + row;
    const float* srow = &stage[row * STAGE_PITCH + hh * 64];
    if (MODE == 0) {
        const float pos = (float)(m & (S_ - 1));
        float vb[64], rb[64];
        #pragma unroll
        for (int d = 0; d < 32; d++) {
            const float qlo = srow[d];
            const float qhi = srow[d + 32];
            const float inv = exp2f((float)d * -0.41524101186920654f);
            float sn, cs;
            sincosf(pos * inv, &sn, &cs);
            vb[d] = qlo;      vb[d + 32] = qhi;
            rb[d] = qlo * cs - qhi * sn;
            rb[d + 32] = qhi * cs + qlo * sn;
        }
        float* vp = &g_v[(size_t)m * HID_ + n0 + hh * 64];
        float* rp = &g_qrot[(size_t)m * HID_ + n0 + hh * 64];
        #pragma unroll
        for (int q = 0; q < 16; q++) {
            *(float4*)(vp + q * 4) = *(float4*)&vb[q * 4];
            *(float4*)(rp + q * 4) = *(float4*)&rb[q * 4];
        }
    } else {
        float* op = &out[(size_t)m * HID_ + n0 + hh * 64];
        #pragma unroll
        for (int q = 0; q < 16; q++) {
            float4 f = make_float4(srow[q * 4], srow[q * 4 + 1],
                                   srow[q * 4 + 2], srow[q * 4 + 3]);
            *(float4*)(op + q * 4) = f;
        }
    }
}

// ---------------------------------------------------------------------------
// Sliding-window attention (unchanged, fp32).
// ---------------------------------------------------------------------------
#define ATTN_SMEM_FLOATS (64 * 65 * 2 + 64 * 193)

__global__ __launch_bounds__(256)
void attn_kernel() {
    extern __shared__ float smf[];
    float* Qs  = smf;
    float* KVs = Qs + 64 * 65;
    float* Ps  = KVs + 64 * 65;

    const int t0 = blockIdx.x * 64;
    const int bh = blockIdx.y;
    const int b = bh / NH_, h = bh % NH_;
    const int tid = threadIdx.x;
    const int tx = tid & 15, ty = tid >> 4;

    const float* qbase = g_qrot + b * (S_ * HID_) + h * HD_;
    const float* vbase = g_v    + b * (S_ * HID_) + h * HD_;

    for (int idx = tid; idx < 64 * 64; idx += 256) {
        int r = idx >> 6, c = idx & 63;
        Qs[r * 65 + c] = qbase[(t0 + r) * HID_ + c];
    }

    for (int kc = 0; kc < 3; kc++) {
        int s0 = t0 - 64 + kc * 64;
        __syncthreads();
        for (int idx = tid; idx < 64 * 64; idx += 256) {
            int r = idx >> 6, c = idx & 63;
            int s = s0 + r;
            KVs[r * 65 + c] = ((unsigned)s < (unsigned)S_)
                              ? qbase[s * HID_ + c] : 0.0f;
        }
        __syncthreads();

        float acc[4][4] = {};
        #pragma unroll
        for (int dd = 0; dd < 64; dd++) {
            float a[4], bb[4];
            #pragma unroll
            for (int i = 0; i < 4; i++) a[i] = Qs[(ty + 16 * i) * 65 + dd];
            #pragma unroll
            for (int j = 0; j < 4; j++) bb[j] = KVs[(tx + 16 * j) * 65 + dd];
            #pragma unroll
            for (int i = 0; i < 4; i++)
                #pragma unroll
                for (int j = 0; j < 4; j++) acc[i][j] += a[i] * bb[j];
        }
        #pragma unroll
        for (int i = 0; i < 4; i++) {
            int qi = ty + 16 * i, t = t0 + qi;
            #pragma unroll
            for (int j = 0; j < 4; j++) {
                int kj = tx + 16 * j, s = s0 + kj;
                int dist = t - s; if (dist < 0) dist = -dist;
                bool valid = ((unsigned)s < (unsigned)S_) && (dist <= WHALF);
                Ps[qi * 193 + kc * 64 + kj] = valid ? acc[i][j] * 0.125f : -1e30f;
            }
        }
    }
    __syncthreads();

    const int warp = tid >> 5, lane = tid & 31;
    for (int r = warp; r < 64; r += 8) {
        float mx = -1e30f;
        for (int c = lane; c < 192; c += 32) mx = fmaxf(mx, Ps[r * 193 + c]);
        #pragma unroll
        for (int off = 16; off; off >>= 1)
            mx = fmaxf(mx, __shfl_xor_sync(0xffffffffu, mx, off));
        float sum = 0.0f;
        for (int c = lane; c < 192; c += 32) {
            float e = __expf(Ps[r * 193 + c] - mx);
            Ps[r * 193 + c] = e;
            sum += e;
        }
        #pragma unroll
        for (int off = 16; off; off >>= 1)
            sum += __shfl_xor_sync(0xffffffffu, sum, off);
        float inv = 1.0f / sum;
        for (int c = lane; c < 192; c += 32) Ps[r * 193 + c] *= inv;
    }
    __syncthreads();

    float o[4][4] = {};
    for (int kc = 0; kc < 3; kc++) {
        int s0 = t0 - 64 + kc * 64;
        for (int idx = tid; idx < 64 * 64; idx += 256) {
            int r = idx >> 6, c = idx & 63;
            int s = s0 + r;
            KVs[r * 65 + c] = ((unsigned)s < (unsigned)S_)
                              ? vbase[s * HID_ + c] : 0.0f;
        }
        __syncthreads();
        #pragma unroll
        for (int kk = 0; kk < 64; kk++) {
            float a[4], bb[4];
            #pragma unroll
            for (int i = 0; i < 4; i++)
                a[i] = Ps[(ty + 16 * i) * 193 + kc * 64 + kk];
            #pragma unroll
            for (int j = 0; j < 4; j++)
                bb[j] = KVs[kk * 65 + tx + 16 * j];
            #pragma unroll
            for (int i = 0; i < 4; i++)
                #pragma unroll
                for (int j = 0; j < 4; j++) o[i][j] += a[i] * bb[j];
        }
        __syncthreads();
    }

    float* obase = g_attn + b * (S_ * HID_) + h * HD_;
    #pragma unroll
    for (int i = 0; i < 4; i++)
        #pragma unroll
        for (int j = 0; j < 4; j++)
            obase[(t0 + ty + 16 * i) * HID_ + tx + 16 * j] = o[i][j];
}

// ---------------------------------------------------------------------------
extern "C" void kernel_launch(void* const* d_in, const int* in_sizes, int n_in,
                              void* d_out, int out_size) {
    const float* hidden = (const float*)d_in[0];   // [B,S,HID]
    const float* Wq     = (const float*)d_in[1];   // [HID,HID]
    const float* Wo     = (const float*)d_in[2];   // [HID,HID]
    float* out = (float*)d_out;
    (void)in_sizes; (void)n_in; (void)out_size;

    const size_t attn_smem = ATTN_SMEM_FLOATS * sizeof(float);
    cudaFuncSetAttribute(attn_kernel,
                         cudaFuncAttributeMaxDynamicSharedMemorySize,
                         (int)attn_smem);
    cudaFuncSetAttribute(gemm_mma<0>,
                         cudaFuncAttributeMaxDynamicSharedMemorySize, GT_SMEM);
    cudaFuncSetAttribute(gemm_mma<1>,
                         cudaFuncAttributeMaxDynamicSharedMemorySize, GT_SMEM);

    // bf16 split converts — device buffers selected inside the kernels
    split_bf16<0, 0><<<(M_ * HID_ / 4 + 255) / 256, 256>>>(hidden, M_ * HID_);
    split_bf16<0, 1><<<(HID_ * HID_ / 4 + 255) / 256, 256>>>(Wq, HID_ * HID_);
    split_bf16<0, 2><<<(HID_ * HID_ / 4 + 255) / 256, 256>>>(Wo, HID_ * HID_);

    dim3 gemm_grid(HID_ / 128, M_ / 128);   // (6, 32) = 192 CTAs, one wave @2/SM
    gemm_mma<0><<<gemm_grid, 256, GT_SMEM>>>(nullptr);

    dim3 attn_grid(S_ / 64, B_ * NH_);      // (32, 24)
    attn_kernel<<<attn_grid, 256, attn_smem>>>();

    split_bf16<1, 0><<<(M_ * HID_ / 4 + 255) / 256, 256>>>(nullptr, M_ * HID_);
    gemm_mma<1><<<gemm_grid, 256, GT_SMEM>>>(out);
}

// round 10
// speedup vs baseline: 2.8591x; 1.6028x over previous
#include <cuda_runtime.h>
#include <cuda_bf16.h>
#include <math.h>
#include <stdint.h>

#define B_    2
#define S_    2048
#define HID_  768
#define NH_   12
#define HD_   64
#define M_    (B_ * S_)          // 4096 rows
#define WHALF 64                 // WINDOW/2

// ---------------- device scratch (no allocations allowed) ------------------
__device__ __align__(16) float g_attn[M_ * HID_];   // attention output (fp32)

// bf16 split operands for projection GEMMs
__device__ __align__(16) __nv_bfloat16 gAh[M_ * HID_];
__device__ __align__(16) __nv_bfloat16 gAl[M_ * HID_];
__device__ __align__(16) __nv_bfloat16 gW1h[HID_ * HID_];
__device__ __align__(16) __nv_bfloat16 gW1l[HID_ * HID_];
__device__ __align__(16) __nv_bfloat16 gW2h[HID_ * HID_];
__device__ __align__(16) __nv_bfloat16 gW2l[HID_ * HID_];

// bf16 splits for attention (written by gemm<0> epilogue)
__device__ __align__(16) __nv_bfloat16 gKh[M_ * HID_];  // q_rot hi (= k)
__device__ __align__(16) __nv_bfloat16 gKl[M_ * HID_];  // q_rot lo
__device__ __align__(16) __nv_bfloat16 gVh[M_ * HID_];  // v hi
__device__ __align__(16) __nv_bfloat16 gVl[M_ * HID_];  // v lo

// ---------------- PTX helpers (baseline ISA only) --------------------------
__device__ __forceinline__ uint32_t smem_u32(const void* p) {
    uint32_t a;
    asm("{ .reg .u64 t; cvta.to.shared.u64 t, %1; cvt.u32.u64 %0, t; }"
        : "=r"(a) : "l"(p));
    return a;
}
__device__ __forceinline__ void ldmx4(uint32_t r[4], uint32_t addr) {
    asm volatile("ldmatrix.sync.aligned.m8n8.x4.shared.b16 {%0,%1,%2,%3}, [%4];"
                 : "=r"(r[0]), "=r"(r[1]), "=r"(r[2]), "=r"(r[3]) : "r"(addr));
}
__device__ __forceinline__ void ldmx2(uint32_t r[2], uint32_t addr) {
    asm volatile("ldmatrix.sync.aligned.m8n8.x2.shared.b16 {%0,%1}, [%2];"
                 : "=r"(r[0]), "=r"(r[1]) : "r"(addr));
}
__device__ __forceinline__ void ldmx2t(uint32_t r[2], uint32_t addr) {
    asm volatile("ldmatrix.sync.aligned.m8n8.x2.trans.shared.b16 {%0,%1}, [%2];"
                 : "=r"(r[0]), "=r"(r[1]) : "r"(addr));
}
__device__ __forceinline__ void mma_bf16(float c[4], const uint32_t a[4],
                                         const uint32_t b[2]) {
    asm volatile(
        "mma.sync.aligned.m16n8k16.row.col.f32.bf16.bf16.f32 "
        "{%0,%1,%2,%3}, {%4,%5,%6,%7}, {%8,%9}, {%0,%1,%2,%3};"
        : "+f"(c[0]), "+f"(c[1]), "+f"(c[2]), "+f"(c[3])
        : "r"(a[0]), "r"(a[1]), "r"(a[2]), "r"(a[3]), "r"(b[0]), "r"(b[1]));
}
__device__ __forceinline__ void cp16(uint32_t dst, const void* src) {
    asm volatile("cp.async.cg.shared.global [%0], [%1], 16;"
                 :: "r"(dst), "l"(src));
}
#define CP_COMMIT() asm volatile("cp.async.commit_group;" ::: "memory")
#define CP_WAIT1()  asm volatile("cp.async.wait_group 1;" ::: "memory")

#define SWZ64(off)  ((off) ^ (((off) >> 3) & 0x30))
#define SWZ128(off) ((off) ^ (((off) >> 3) & 0x70))

__device__ __forceinline__ __nv_bfloat16 bhi(float x) { return __float2bfloat16(x); }

// ---------------------------------------------------------------------------
// split convert: fp32 -> bf16 hi + lo. Device symbols selected in device code.
// SRC: 0 = srcin param, 1 = g_attn.   DST: 0 = gA*, 1 = gW1*, 2 = gW2*.
// ---------------------------------------------------------------------------
template<int SRC, int DST>
__global__ __launch_bounds__(256)
void split_bf16(const float* __restrict__ srcin, int n) {
    const float* __restrict__ src = (SRC == 0) ? srcin : (const float*)g_attn;
    __nv_bfloat16* __restrict__ hi = (DST == 0) ? gAh : (DST == 1) ? gW1h : gW2h;
    __nv_bfloat16* __restrict__ lo = (DST == 0) ? gAl : (DST == 1) ? gW1l : gW2l;
    int i = (blockIdx.x * 256 + threadIdx.x) * 4;
    if (i >= n) return;
    float4 v = *(const float4*)(src + i);
    __nv_bfloat16 h0 = bhi(v.x), h1 = bhi(v.y), h2 = bhi(v.z), h3 = bhi(v.w);
    __nv_bfloat16 l0 = bhi(v.x - __bfloat162float(h0));
    __nv_bfloat16 l1 = bhi(v.y - __bfloat162float(h1));
    __nv_bfloat16 l2 = bhi(v.z - __bfloat162float(h2));
    __nv_bfloat16 l3 = bhi(v.w - __bfloat162float(h3));
    *(__nv_bfloat162*)(hi + i)     = __nv_bfloat162(h0, h1);
    *(__nv_bfloat162*)(hi + i + 2) = __nv_bfloat162(h2, h3);
    *(__nv_bfloat162*)(lo + i)     = __nv_bfloat162(l0, l1);
    *(__nv_bfloat162*)(lo + i + 2) = __nv_bfloat162(l2, l3);
}

// ---------------------------------------------------------------------------
// Pipelined HMMA GEMM (as round 9). MODE 0 epilogue now emits bf16 splits of
// RoPE(q) -> gKh/gKl and v -> gVh/gVl (no fp32 intermediates).
// ---------------------------------------------------------------------------
#define TILE_B   8192
#define STAGE_B  (4 * TILE_B)
#define STAGE_PITCH 132
#define GT_SMEM (128 * STAGE_PITCH * 4)
#define NCHUNK (HID_ / 32)

template<int MODE>
__global__ __launch_bounds__(256, 2)
void gemm_mma(float* __restrict__ out) {
    extern __shared__ __align__(1024) char sm[];
    const uint32_t smb = smem_u32(sm);

    const int n0 = blockIdx.x * 128;
    const int m0 = blockIdx.y * 128;
    const int tid = threadIdx.x;
    const int wid = tid >> 5, lane = tid & 31;
    const int wm = (wid >> 2) * 64;
    const int wn = (wid & 3) * 32;

    const __nv_bfloat16* __restrict__ Bh = (MODE == 0) ? gW1h : gW2h;
    const __nv_bfloat16* __restrict__ Bl = (MODE == 0) ? gW1l : gW2l;

    const int lrow0 = tid >> 2;
    const int lseg  = tid & 3;
    const size_t gA0 = (size_t)(m0 + lrow0) * HID_ + lseg * 8;
    const size_t gA1 = (size_t)(m0 + lrow0 + 64) * HID_ + lseg * 8;
    const size_t gW0 = (size_t)(n0 + lrow0) * HID_ + lseg * 8;
    const size_t gW1v = (size_t)(n0 + lrow0 + 64) * HID_ + lseg * 8;
    const uint32_t so0 = SWZ64((uint32_t)(lrow0 * 64 + lseg * 16));
    const uint32_t so1 = SWZ64((uint32_t)((lrow0 + 64) * 64 + lseg * 16));

    #define LOAD_CHUNK(cc, bufb)                                              \
    {                                                                         \
        const int k0_ = (cc) * 32;                                            \
        const uint32_t s_ = smb + 1024 + (bufb) * STAGE_B;                    \
        cp16(s_ + so0,              gAh + gA0 + k0_);                         \
        cp16(s_ + so1,              gAh + gA1 + k0_);                         \
        cp16(s_ + TILE_B + so0,     gAl + gA0 + k0_);                         \
        cp16(s_ + TILE_B + so1,     gAl + gA1 + k0_);                         \
        cp16(s_ + 2 * TILE_B + so0, Bh + gW0 + k0_);                          \
        cp16(s_ + 2 * TILE_B + so1, Bh + gW1v + k0_);                         \
        cp16(s_ + 3 * TILE_B + so0, Bl + gW0 + k0_);                          \
        cp16(s_ + 3 * TILE_B + so1, Bl + gW1v + k0_);                         \
    }

    float acc[4][4][4] = {};
    const int arow = lane & 15;
    const int ahalf = (lane >> 4) << 4;
    const int brow = lane & 7;
    const int bhalf = ((lane >> 3) & 1) << 4;

    LOAD_CHUNK(0, 0); CP_COMMIT();
    LOAD_CHUNK(1, 1); CP_COMMIT();

    for (int c = 0; c < NCHUNK; c++) {
        const int buf = c & 1;
        const uint32_t uAh = smb + 1024 + buf * STAGE_B;
        const uint32_t uAl = uAh + TILE_B;
        const uint32_t uWh = uAh + 2 * TILE_B;
        const uint32_t uWl = uAh + 3 * TILE_B;

        CP_WAIT1();
        __syncthreads();

        #pragma unroll
        for (int ks = 0; ks < 2; ks++) {
            const int kb = ks * 32;
            uint32_t ah[4][4], bh2[4][2], bl2[4][2];
            #pragma unroll
            for (int mt = 0; mt < 4; mt++) {
                const int r = wm + mt * 16 + arow;
                ldmx4(ah[mt], uAh + SWZ64(r * 64 + kb + ahalf));
            }
            #pragma unroll
            for (int nt = 0; nt < 4; nt++) {
                const int r = wn + nt * 8 + brow;
                const uint32_t off = SWZ64(r * 64 + kb + bhalf);
                ldmx2(bh2[nt], uWh + off);
                ldmx2(bl2[nt], uWl + off);
            }
            #pragma unroll
            for (int mt = 0; mt < 4; mt++)
                #pragma unroll
                for (int nt = 0; nt < 4; nt++) {
                    mma_bf16(acc[mt][nt], ah[mt], bh2[nt]);
                    mma_bf16(acc[mt][nt], ah[mt], bl2[nt]);
                }
            uint32_t al[4];
            #pragma unroll
            for (int mt = 0; mt < 4; mt++) {
                const int r = wm + mt * 16 + arow;
                ldmx4(al, uAl + SWZ64(r * 64 + kb + ahalf));
                #pragma unroll
                for (int nt = 0; nt < 4; nt++)
                    mma_bf16(acc[mt][nt], al, bh2[nt]);
            }
        }
        __syncthreads();
        if (c + 2 < NCHUNK) LOAD_CHUNK(c + 2, buf);
        CP_COMMIT();
    }
    #undef LOAD_CHUNK

    // ---- epilogue: stage in smem, then coalesced processing ----
    float* stage = (float*)sm;
    #pragma unroll
    for (int mt = 0; mt < 4; mt++)
        #pragma unroll
        for (int nt = 0; nt < 4; nt++) {
            const int r = wm + mt * 16 + (lane >> 2);
            const int cc = wn + nt * 8 + 2 * (lane & 3);
            *(float2*)&stage[r * STAGE_PITCH + cc] =
                make_float2(acc[mt][nt][0], acc[mt][nt][1]);
            *(float2*)&stage[(r + 8) * STAGE_PITCH + cc] =
                make_float2(acc[mt][nt][2], acc[mt][nt][3]);
        }
    __syncthreads();

    const int row = tid >> 1;
    const int hh  = tid & 1;
    const int m = m0 + row;
    const float* srow = &stage[row * STAGE_PITCH + hh * 64];
    if (MODE == 0) {
        const float pos = (float)(m & (S_ - 1));
        float vb[64], rb[64];
        #pragma unroll
        for (int d = 0; d < 32; d++) {
            const float qlo = srow[d];
            const float qhi = srow[d + 32];
            const float inv = exp2f((float)d * -0.41524101186920654f);
            float sn, cs;
            sincosf(pos * inv, &sn, &cs);
            vb[d] = qlo;      vb[d + 32] = qhi;
            rb[d] = qlo * cs - qhi * sn;
            rb[d + 32] = qhi * cs + qlo * sn;
        }
        const size_t base = (size_t)m * HID_ + n0 + hh * 64;
        #pragma unroll
        for (int q = 0; q < 8; q++) {
            __nv_bfloat162 kh4[4], kl4[4], vh4[4], vl4[4];
            #pragma unroll
            for (int e = 0; e < 4; e++) {
                float v0 = vb[q * 8 + 2 * e], v1 = vb[q * 8 + 2 * e + 1];
                float r0 = rb[q * 8 + 2 * e], r1 = rb[q * 8 + 2 * e + 1];
                __nv_bfloat16 vh0 = bhi(v0), vh1 = bhi(v1);
                __nv_bfloat16 rh0 = bhi(r0), rh1 = bhi(r1);
                vh4[e] = __nv_bfloat162(vh0, vh1);
                vl4[e] = __nv_bfloat162(bhi(v0 - __bfloat162float(vh0)),
                                        bhi(v1 - __bfloat162float(vh1)));
                kh4[e] = __nv_bfloat162(rh0, rh1);
                kl4[e] = __nv_bfloat162(bhi(r0 - __bfloat162float(rh0)),
                                        bhi(r1 - __bfloat162float(rh1)));
            }
            *(int4*)(gKh + base + q * 8) = *(int4*)kh4;
            *(int4*)(gKl + base + q * 8) = *(int4*)kl4;
            *(int4*)(gVh + base + q * 8) = *(int4*)vh4;
            *(int4*)(gVl + base + q * 8) = *(int4*)vl4;
        }
    } else {
        float* op = &out[(size_t)m * HID_ + n0 + hh * 64];
        #pragma unroll
        for (int q = 0; q < 16; q++) {
            float4 f = make_float4(srow[q * 4], srow[q * 4 + 1],
                                   srow[q * 4 + 2], srow[q * 4 + 3]);
            *(float4*)(op + q * 4) = f;
        }
    }
}

// ---------------------------------------------------------------------------
// HMMA sliding-window attention. One block = 64 queries of one (b,h).
// Scores = 3-term bf16 split; fp32 register softmax; P split -> PV 3-term.
// smem: Qh Ql (8KB ea), KVh KVl (8KB ea, K then V), ph pl (25.6KB ea), red 1KB
// ---------------------------------------------------------------------------
#define QH_OFF  0
#define QL_OFF  8192
#define KVH_OFF 16384
#define KVL_OFF 24576
#define PH_OFF  32768
#define PL_OFF  58368
#define RED_OFF 83968
#define AT_SMEM 84992
#define P_PITCH 400        // bytes per P row (192 bf16 used)

__global__ __launch_bounds__(256, 2)
void attn_mma() {
    extern __shared__ __align__(1024) char sm[];
    const uint32_t smb = smem_u32(sm);

    const int t0 = blockIdx.x * 64;
    const int bh = blockIdx.y;
    const int b = bh / NH_, h = bh % NH_;
    const int tid = threadIdx.x;
    const int wid = tid >> 5, lane = tid & 31;
    const int wm2 = (wid >> 2) * 32;   // query offset (0/32)
    const int wg  = wid & 3;           // col-group
    const int wn2 = wg * 16;           // keys within chunk (score phase)

    const int arow = lane & 15;
    const int ahalf = (lane >> 4) << 4;
    const int brow = lane & 7;
    const int bhalf = ((lane >> 3) & 1) << 4;

    float* red = (float*)(sm + RED_OFF);

    // ---- load Q tiles (rows t0..t0+63, always in range) ----
    #pragma unroll
    for (int t = 0; t < 2; t++) {
        const int seg = tid + t * 256;
        const int row = seg >> 3, sc = seg & 7;
        const size_t g = ((size_t)(b * S_ + t0 + row)) * HID_ + h * 64 + sc * 8;
        const uint32_t off = SWZ128((uint32_t)(row * 128 + sc * 16));
        *(int4*)(sm + QH_OFF + off) = *(const int4*)(gKh + g);
        *(int4*)(sm + QL_OFF + off) = *(const int4*)(gKl + g);
    }

    // ---- score phase: 3 key chunks ----
    float sacc[3][2][2][4] = {};
    for (int kc = 0; kc < 3; kc++) {
        const int s0 = t0 - 64 + kc * 64;
        __syncthreads();
        #pragma unroll
        for (int t = 0; t < 2; t++) {
            const int seg = tid + t * 256;
            const int row = seg >> 3, sc = seg & 7;
            const int s = s0 + row;
            int4 vh = make_int4(0, 0, 0, 0), vl = make_int4(0, 0, 0, 0);
            if ((unsigned)s < (unsigned)S_) {
                const size_t g = ((size_t)(b * S_ + s)) * HID_ + h * 64 + sc * 8;
                vh = *(const int4*)(gKh + g);
                vl = *(const int4*)(gKl + g);
            }
            const uint32_t off = SWZ128((uint32_t)(row * 128 + sc * 16));
            *(int4*)(sm + KVH_OFF + off) = vh;
            *(int4*)(sm + KVL_OFF + off) = vl;
        }
        __syncthreads();

        #pragma unroll
        for (int ks = 0; ks < 4; ks++) {
            const int kb = ks * 32;
            uint32_t qh_[2][4], ql_[2][4], kh_[2][2], kl_[2][2];
            #pragma unroll
            for (int mt = 0; mt < 2; mt++) {
                const uint32_t ao = SWZ128((wm2 + mt * 16 + arow) * 128 + kb + ahalf);
                ldmx4(qh_[mt], smb + QH_OFF + ao);
                ldmx4(ql_[mt], smb + QL_OFF + ao);
            }
            #pragma unroll
            for (int nt = 0; nt < 2; nt++) {
                const uint32_t bo = SWZ128((wn2 + nt * 8 + brow) * 128 + kb + bhalf);
                ldmx2(kh_[nt], smb + KVH_OFF + bo);
                ldmx2(kl_[nt], smb + KVL_OFF + bo);
            }
            #pragma unroll
            for (int mt = 0; mt < 2; mt++)
                #pragma unroll
                for (int nt = 0; nt < 2; nt++) {
                    mma_bf16(sacc[kc][mt][nt], qh_[mt], kh_[nt]);
                    mma_bf16(sacc[kc][mt][nt], qh_[mt], kl_[nt]);
                    mma_bf16(sacc[kc][mt][nt], ql_[mt], kh_[nt]);
                }
        }
    }

    // ---- mask + scale (in registers) ----
    #pragma unroll
    for (int kc = 0; kc < 3; kc++)
        #pragma unroll
        for (int mt = 0; mt < 2; mt++)
            #pragma unroll
            for (int nt = 0; nt < 2; nt++)
                #pragma unroll
                for (int j = 0; j < 4; j++) {
                    const int row = wm2 + mt * 16 + (lane >> 2) + (j >> 1) * 8;
                    const int col = kc * 64 + wn2 + nt * 8 + 2 * (lane & 3) + (j & 1);
                    const int t = t0 + row;
                    const int s = t0 - 64 + col;
                    int dist = t - s; if (dist < 0) dist = -dist;
                    const bool valid = ((unsigned)s < (unsigned)S_) && (dist <= WHALF);
                    sacc[kc][mt][nt][j] = valid ? sacc[kc][mt][nt][j] * 0.125f : -1e30f;
                }

    // ---- softmax: row max ----
    float rmax[2][2];
    #pragma unroll
    for (int mt = 0; mt < 2; mt++)
        #pragma unroll
        for (int hf = 0; hf < 2; hf++) {
            float m = -1e30f;
            #pragma unroll
            for (int kc = 0; kc < 3; kc++)
                #pragma unroll
                for (int nt = 0; nt < 2; nt++) {
                    m = fmaxf(m, sacc[kc][mt][nt][hf * 2]);
                    m = fmaxf(m, sacc[kc][mt][nt][hf * 2 + 1]);
                }
            m = fmaxf(m, __shfl_xor_sync(0xffffffffu, m, 1));
            m = fmaxf(m, __shfl_xor_sync(0xffffffffu, m, 2));
            rmax[mt][hf] = m;
        }
    #pragma unroll
    for (int mt = 0; mt < 2; mt++)
        #pragma unroll
        for (int hf = 0; hf < 2; hf++)
            red[(wm2 + mt * 16 + (lane >> 2) + hf * 8) * 4 + wg] = rmax[mt][hf];
    __syncthreads();
    #pragma unroll
    for (int mt = 0; mt < 2; mt++)
        #pragma unroll
        for (int hf = 0; hf < 2; hf++) {
            const int r = wm2 + mt * 16 + (lane >> 2) + hf * 8;
            rmax[mt][hf] = fmaxf(fmaxf(red[r * 4], red[r * 4 + 1]),
                                 fmaxf(red[r * 4 + 2], red[r * 4 + 3]));
        }
    __syncthreads();

    // ---- exp + row sum ----
    float rsum[2][2];
    #pragma unroll
    for (int mt = 0; mt < 2; mt++)
        #pragma unroll
        for (int hf = 0; hf < 2; hf++) {
            float s = 0.0f;
            #pragma unroll
            for (int kc = 0; kc < 3; kc++)
                #pragma unroll
                for (int nt = 0; nt < 2; nt++)
                    #pragma unroll
                    for (int e = 0; e < 2; e++) {
                        float p = __expf(sacc[kc][mt][nt][hf * 2 + e] - rmax[mt][hf]);
                        sacc[kc][mt][nt][hf * 2 + e] = p;
                        s += p;
                    }
            s += __shfl_xor_sync(0xffffffffu, s, 1);
            s += __shfl_xor_sync(0xffffffffu, s, 2);
            rsum[mt][hf] = s;
        }
    #pragma unroll
    for (int mt = 0; mt < 2; mt++)
        #pragma unroll
        for (int hf = 0; hf < 2; hf++)
            red[(wm2 + mt * 16 + (lane >> 2) + hf * 8) * 4 + wg] = rsum[mt][hf];
    __syncthreads();
    #pragma unroll
    for (int mt = 0; mt < 2; mt++)
        #pragma unroll
        for (int hf = 0; hf < 2; hf++) {
            const int r = wm2 + mt * 16 + (lane >> 2) + hf * 8;
            rsum[mt][hf] = 1.0f / (red[r * 4] + red[r * 4 + 1] +
                                   red[r * 4 + 2] + red[r * 4 + 3]);
        }

    // ---- normalize, split to bf16, store ph/pl ----
    #pragma unroll
    for (int kc = 0; kc < 3; kc++)
        #pragma unroll
        for (int mt = 0; mt < 2; mt++)
            #pragma unroll
            for (int nt = 0; nt < 2; nt++)
                #pragma unroll
                for (int hf = 0; hf < 2; hf++) {
                    const int row = wm2 + mt * 16 + (lane >> 2) + hf * 8;
                    const int col = kc * 64 + wn2 + nt * 8 + 2 * (lane & 3);
                    float p0 = sacc[kc][mt][nt][hf * 2]     * rsum[mt][hf];
                    float p1 = sacc[kc][mt][nt][hf * 2 + 1] * rsum[mt][hf];
                    __nv_bfloat16 h0 = bhi(p0), h1 = bhi(p1);
                    __nv_bfloat162 ph2(h0, h1);
                    __nv_bfloat162 pl2(bhi(p0 - __bfloat162float(h0)),
                                       bhi(p1 - __bfloat162float(h1)));
                    *(__nv_bfloat162*)(sm + PH_OFF + row * P_PITCH + col * 2) = ph2;
                    *(__nv_bfloat162*)(sm + PL_OFF + row * P_PITCH + col * 2) = pl2;
                }

    // ---- PV phase: O = P @ V, 3 chunks of 64 keys ----
    const int wn2v = wg * 16;   // dims 0..63
    float oacc[2][2][4] = {};
    for (int kc = 0; kc < 3; kc++) {
        const int s0 = t0 - 64 + kc * 64;
        __syncthreads();   // ph stores visible / prev V reads done
        #pragma unroll
        for (int t = 0; t < 2; t++) {
            const int seg = tid + t * 256;
            const int row = seg >> 3, sc = seg & 7;
            const int s = s0 + row;
            int4 vh = make_int4(0, 0, 0, 0), vl = make_int4(0, 0, 0, 0);
            if ((unsigned)s < (unsigned)S_) {
                const size_t g = ((size_t)(b * S_ + s)) * HID_ + h * 64 + sc * 8;
                vh = *(const int4*)(gVh + g);
                vl = *(const int4*)(gVl + g);
            }
            const uint32_t off = SWZ128((uint32_t)(row * 128 + sc * 16));
            *(int4*)(sm + KVH_OFF + off) = vh;
            *(int4*)(sm + KVL_OFF + off) = vl;
        }
        __syncthreads();

        #pragma unroll
        for (int ks = 0; ks < 4; ks++) {
            uint32_t pa_h[2][4], pa_l[2][4], vh_[2][2], vl_[2][2];
            #pragma unroll
            for (int mt = 0; mt < 2; mt++) {
                const uint32_t ao = (uint32_t)((wm2 + mt * 16 + arow) * P_PITCH
                                               + kc * 128 + ks * 32 + ahalf);
                ldmx4(pa_h[mt], smb + PH_OFF + ao);
                ldmx4(pa_l[mt], smb + PL_OFF + ao);
            }
            const int krow = ks * 16 + arow;   // lane&15 selects key row
            #pragma unroll
            for (int nt = 0; nt < 2; nt++) {
                const uint32_t bo = SWZ128((uint32_t)(krow * 128
                                           + (wn2v + nt * 8) * 2));
                ldmx2t(vh_[nt], smb + KVH_OFF + bo);
                ldmx2t(vl_[nt], smb + KVL_OFF + bo);
            }
            #pragma unroll
            for (int mt = 0; mt < 2; mt++)
                #pragma unroll
                for (int nt = 0; nt < 2; nt++) {
                    mma_bf16(oacc[mt][nt], pa_h[mt], vh_[nt]);
                    mma_bf16(oacc[mt][nt], pa_h[mt], vl_[nt]);
                    mma_bf16(oacc[mt][nt], pa_l[mt], vh_[nt]);
                }
        }
    }

    // ---- epilogue: stage O (reuse ph region), coalesced fp32 store ----
    __syncthreads();
    float* stage = (float*)(sm + PH_OFF);   // [64][68]
    #pragma unroll
    for (int mt = 0; mt < 2; mt++)
        #pragma unroll
        for (int nt = 0; nt < 2; nt++) {
            const int r = wm2 + mt * 16 + (lane >> 2);
            const int c = wn2v + nt * 8 + 2 * (lane & 3);
            *(float2*)&stage[r * 68 + c] = make_float2(oacc[mt][nt][0], oacc[mt][nt][1]);
            *(float2*)&stage[(r + 8) * 68 + c] = make_float2(oacc[mt][nt][2], oacc[mt][nt][3]);
        }
    __syncthreads();
    {
        const int row = tid >> 2, q4 = tid & 3;
        float* op = &g_attn[((size_t)(b * S_ + t0 + row)) * HID_ + h * 64 + q4 * 16];
        const float* sp = &stage[row * 68 + q4 * 16];
        #pragma unroll
        for (int q = 0; q < 4; q++) {
            float4 f = make_float4(sp[q * 4], sp[q * 4 + 1], sp[q * 4 + 2], sp[q * 4 + 3]);
            *(float4*)(op + q * 4) = f;
        }
    }
}

// ---------------------------------------------------------------------------
extern "C" void kernel_launch(void* const* d_in, const int* in_sizes, int n_in,
                              void* d_out, int out_size) {
    const float* hidden = (const float*)d_in[0];
    const float* Wq     = (const float*)d_in[1];
    const float* Wo     = (const float*)d_in[2];
    float* out = (float*)d_out;
    (void)in_sizes; (void)n_in; (void)out_size;

    cudaFuncSetAttribute(gemm_mma<0>,
                         cudaFuncAttributeMaxDynamicSharedMemorySize, GT_SMEM);
    cudaFuncSetAttribute(gemm_mma<1>,
                         cudaFuncAttributeMaxDynamicSharedMemorySize, GT_SMEM);
    cudaFuncSetAttribute(attn_mma,
                         cudaFuncAttributeMaxDynamicSharedMemorySize, AT_SMEM);

    split_bf16<0, 0><<<(M_ * HID_ / 4 + 255) / 256, 256>>>(hidden, M_ * HID_);
    split_bf16<0, 1><<<(HID_ * HID_ / 4 + 255) / 256, 256>>>(Wq, HID_ * HID_);
    split_bf16<0, 2><<<(HID_ * HID_ / 4 + 255) / 256, 256>>>(Wo, HID_ * HID_);

    dim3 gemm_grid(HID_ / 128, M_ / 128);
    gemm_mma<0><<<gemm_grid, 256, GT_SMEM>>>(nullptr);

    dim3 attn_grid(S_ / 64, B_ * NH_);
    attn_mma<<<attn_grid, 256, AT_SMEM>>>();

    split_bf16<1, 0><<<(M_ * HID_ / 4 + 255) / 256, 256>>>(nullptr, M_ * HID_);
    gemm_mma<1><<<gemm_grid, 256, GT_SMEM>>>(out);
}

// round 11
// speedup vs baseline: 2.8951x; 1.0126x over previous
#include <cuda_runtime.h>
#include <cuda_bf16.h>
#include <math.h>
#include <stdint.h>

#define B_    2
#define S_    2048
#define HID_  768
#define NH_   12
#define HD_   64
#define M_    (B_ * S_)          // 4096 rows
#define WHALF 64                 // WINDOW/2

// ---------------- device scratch (no allocations allowed) ------------------
// bf16 split operands for projection GEMMs
__device__ __align__(16) __nv_bfloat16 gAh[M_ * HID_];   // A operand hi
__device__ __align__(16) __nv_bfloat16 gAl[M_ * HID_];   // A operand lo
__device__ __align__(16) __nv_bfloat16 gW1h[HID_ * HID_];
__device__ __align__(16) __nv_bfloat16 gW1l[HID_ * HID_];
__device__ __align__(16) __nv_bfloat16 gW2h[HID_ * HID_];
__device__ __align__(16) __nv_bfloat16 gW2l[HID_ * HID_];

// bf16 splits for attention (written by gemm<0> epilogue)
__device__ __align__(16) __nv_bfloat16 gKh[M_ * HID_];  // q_rot hi (= k)
__device__ __align__(16) __nv_bfloat16 gKl[M_ * HID_];  // q_rot lo
__device__ __align__(16) __nv_bfloat16 gVh[M_ * HID_];  // v hi
__device__ __align__(16) __nv_bfloat16 gVl[M_ * HID_];  // v lo

// ---------------- PTX helpers (baseline ISA only) --------------------------
__device__ __forceinline__ uint32_t smem_u32(const void* p) {
    uint32_t a;
    asm("{ .reg .u64 t; cvta.to.shared.u64 t, %1; cvt.u32.u64 %0, t; }"
        : "=r"(a) : "l"(p));
    return a;
}
__device__ __forceinline__ void ldmx4(uint32_t r[4], uint32_t addr) {
    asm volatile("ldmatrix.sync.aligned.m8n8.x4.shared.b16 {%0,%1,%2,%3}, [%4];"
                 : "=r"(r[0]), "=r"(r[1]), "=r"(r[2]), "=r"(r[3]) : "r"(addr));
}
__device__ __forceinline__ void ldmx2(uint32_t r[2], uint32_t addr) {
    asm volatile("ldmatrix.sync.aligned.m8n8.x2.shared.b16 {%0,%1}, [%2];"
                 : "=r"(r[0]), "=r"(r[1]) : "r"(addr));
}
__device__ __forceinline__ void ldmx2t(uint32_t r[2], uint32_t addr) {
    asm volatile("ldmatrix.sync.aligned.m8n8.x2.trans.shared.b16 {%0,%1}, [%2];"
                 : "=r"(r[0]), "=r"(r[1]) : "r"(addr));
}
__device__ __forceinline__ void mma_bf16(float c[4], const uint32_t a[4],
                                         const uint32_t b[2]) {
    asm volatile(
        "mma.sync.aligned.m16n8k16.row.col.f32.bf16.bf16.f32 "
        "{%0,%1,%2,%3}, {%4,%5,%6,%7}, {%8,%9}, {%0,%1,%2,%3};"
        : "+f"(c[0]), "+f"(c[1]), "+f"(c[2]), "+f"(c[3])
        : "r"(a[0]), "r"(a[1]), "r"(a[2]), "r"(a[3]), "r"(b[0]), "r"(b[1]));
}
__device__ __forceinline__ void cp16(uint32_t dst, const void* src) {
    asm volatile("cp.async.cg.shared.global [%0], [%1], 16;"
                 :: "r"(dst), "l"(src));
}
#define CP_COMMIT() asm volatile("cp.async.commit_group;" ::: "memory")
#define CP_WAIT1()  asm volatile("cp.async.wait_group 1;" ::: "memory")

#define SWZ64(off)  ((off) ^ (((off) >> 3) & 0x30))
#define SWZ128(off) ((off) ^ (((off) >> 3) & 0x70))

__device__ __forceinline__ __nv_bfloat16 bhi(float x) { return __float2bfloat16(x); }

// ---------------------------------------------------------------------------
// split convert: fp32 -> bf16 hi + lo. DST device symbols selected in device
// code only.  DST: 0 = gA*, 1 = gW1*, 2 = gW2*.
// ---------------------------------------------------------------------------
template<int DST>
__global__ __launch_bounds__(256)
void split_bf16(const float* __restrict__ src, int n) {
    __nv_bfloat16* __restrict__ hi = (DST == 0) ? gAh : (DST == 1) ? gW1h : gW2h;
    __nv_bfloat16* __restrict__ lo = (DST == 0) ? gAl : (DST == 1) ? gW1l : gW2l;
    int i = (blockIdx.x * 256 + threadIdx.x) * 4;
    if (i >= n) return;
    float4 v = *(const float4*)(src + i);
    __nv_bfloat16 h0 = bhi(v.x), h1 = bhi(v.y), h2 = bhi(v.z), h3 = bhi(v.w);
    __nv_bfloat16 l0 = bhi(v.x - __bfloat162float(h0));
    __nv_bfloat16 l1 = bhi(v.y - __bfloat162float(h1));
    __nv_bfloat16 l2 = bhi(v.z - __bfloat162float(h2));
    __nv_bfloat16 l3 = bhi(v.w - __bfloat162float(h3));
    *(__nv_bfloat162*)(hi + i)     = __nv_bfloat162(h0, h1);
    *(__nv_bfloat162*)(hi + i + 2) = __nv_bfloat162(h2, h3);
    *(__nv_bfloat162*)(lo + i)     = __nv_bfloat162(l0, l1);
    *(__nv_bfloat162*)(lo + i + 2) = __nv_bfloat162(l2, l3);
}

// ---------------------------------------------------------------------------
// Pipelined HMMA GEMM, 3-stage cp.async pipeline (ONE barrier per chunk).
// CTA tile 128x128, K chunks of 32. 8 warps 2(m)x4(n), warp tile 64x32.
// MODE 0: epilogue = RoPE + bf16 splits -> gKh/gKl, gVh/gVl.
// MODE 1: epilogue = fp32 store to out.
// smem: [0,1024) pad, stage s at 1024 + s*32768 (s=0,1,2): Ah,Al,Wh,Wl.
// ---------------------------------------------------------------------------
#define TILE_B   8192
#define STAGE_B  (4 * TILE_B)
#define STAGE_PITCH 132
#define GT_SMEM (1024 + 3 * STAGE_B)        // 99328; epi overlay 67584 fits
#define NCHUNK (HID_ / 32)                  // 24

template<int MODE>
__global__ __launch_bounds__(256, 2)
void gemm_mma(float* __restrict__ out) {
    extern __shared__ __align__(1024) char sm[];
    const uint32_t smb = smem_u32(sm);

    const int n0 = blockIdx.x * 128;
    const int m0 = blockIdx.y * 128;
    const int tid = threadIdx.x;
    const int wid = tid >> 5, lane = tid & 31;
    const int wm = (wid >> 2) * 64;
    const int wn = (wid & 3) * 32;

    const __nv_bfloat16* __restrict__ Bh = (MODE == 0) ? gW1h : gW2h;
    const __nv_bfloat16* __restrict__ Bl = (MODE == 0) ? gW1l : gW2l;

    const int lrow0 = tid >> 2;
    const int lseg  = tid & 3;
    const size_t gA0 = (size_t)(m0 + lrow0) * HID_ + lseg * 8;
    const size_t gA1 = (size_t)(m0 + lrow0 + 64) * HID_ + lseg * 8;
    const size_t gW0 = (size_t)(n0 + lrow0) * HID_ + lseg * 8;
    const size_t gW1v = (size_t)(n0 + lrow0 + 64) * HID_ + lseg * 8;
    const uint32_t so0 = SWZ64((uint32_t)(lrow0 * 64 + lseg * 16));
    const uint32_t so1 = SWZ64((uint32_t)((lrow0 + 64) * 64 + lseg * 16));

    #define LOAD_CHUNK(cc, st)                                                \
    {                                                                         \
        const int k0_ = (cc) * 32;                                            \
        const uint32_t s_ = smb + 1024 + (st) * STAGE_B;                      \
        cp16(s_ + so0,              gAh + gA0 + k0_);                         \
        cp16(s_ + so1,              gAh + gA1 + k0_);                         \
        cp16(s_ + TILE_B + so0,     gAl + gA0 + k0_);                         \
        cp16(s_ + TILE_B + so1,     gAl + gA1 + k0_);                         \
        cp16(s_ + 2 * TILE_B + so0, Bh + gW0 + k0_);                         \
        cp16(s_ + 2 * TILE_B + so1, Bh + gW1v + k0_);                        \
        cp16(s_ + 3 * TILE_B + so0, Bl + gW0 + k0_);                         \
        cp16(s_ + 3 * TILE_B + so1, Bl + gW1v + k0_);                        \
    }

    float acc[4][4][4] = {};
    const int arow = lane & 15;
    const int ahalf = (lane >> 4) << 4;
    const int brow = lane & 7;
    const int bhalf = ((lane >> 3) & 1) << 4;

    LOAD_CHUNK(0, 0); CP_COMMIT();
    LOAD_CHUNK(1, 1); CP_COMMIT();

    int st = 0;                    // stage of current chunk
    for (int c = 0; c < NCHUNK; c++) {
        const uint32_t uAh = smb + 1024 + st * STAGE_B;
        const uint32_t uAl = uAh + TILE_B;
        const uint32_t uWh = uAh + 2 * TILE_B;
        const uint32_t uWl = uAh + 3 * TILE_B;

        CP_WAIT1();                // chunk c landed (c+1 may be in flight)
        __syncthreads();           // also: everyone done computing chunk c-1

        // prefetch chunk c+2 into the stage chunk c-1 just vacated
        if (c + 2 < NCHUNK) {
            const int st2 = (st + 2) % 3;
            LOAD_CHUNK(c + 2, st2);
        }
        CP_COMMIT();

        #pragma unroll
        for (int ks = 0; ks < 2; ks++) {
            const int kb = ks * 32;
            uint32_t ah[4][4], bh2[4][2], bl2[4][2];
            #pragma unroll
            for (int mt = 0; mt < 4; mt++) {
                const int r = wm + mt * 16 + arow;
                ldmx4(ah[mt], uAh + SWZ64(r * 64 + kb + ahalf));
            }
            #pragma unroll
            for (int nt = 0; nt < 4; nt++) {
                const int r = wn + nt * 8 + brow;
                const uint32_t off = SWZ64(r * 64 + kb + bhalf);
                ldmx2(bh2[nt], uWh + off);
                ldmx2(bl2[nt], uWl + off);
            }
            // term-major: 16 independent mmas per burst
            #pragma unroll
            for (int mt = 0; mt < 4; mt++)
                #pragma unroll
                for (int nt = 0; nt < 4; nt++)
                    mma_bf16(acc[mt][nt], ah[mt], bh2[nt]);
            #pragma unroll
            for (int mt = 0; mt < 4; mt++)
                #pragma unroll
                for (int nt = 0; nt < 4; nt++)
                    mma_bf16(acc[mt][nt], ah[mt], bl2[nt]);
            uint32_t al[4];
            #pragma unroll
            for (int mt = 0; mt < 4; mt++) {
                const int r = wm + mt * 16 + arow;
                ldmx4(al, uAl + SWZ64(r * 64 + kb + ahalf));
                #pragma unroll
                for (int nt = 0; nt < 4; nt++)
                    mma_bf16(acc[mt][nt], al, bh2[nt]);
            }
        }
        st = (st + 1) % 3;
    }
    #undef LOAD_CHUNK
    __syncthreads();   // stage overlay below reuses the smem

    // ---- epilogue: stage in smem, then coalesced processing ----
    float* stage = (float*)sm;
    #pragma unroll
    for (int mt = 0; mt < 4; mt++)
        #pragma unroll
        for (int nt = 0; nt < 4; nt++) {
            const int r = wm + mt * 16 + (lane >> 2);
            const int cc = wn + nt * 8 + 2 * (lane & 3);
            *(float2*)&stage[r * STAGE_PITCH + cc] =
                make_float2(acc[mt][nt][0], acc[mt][nt][1]);
            *(float2*)&stage[(r + 8) * STAGE_PITCH + cc] =
                make_float2(acc[mt][nt][2], acc[mt][nt][3]);
        }
    __syncthreads();

    const int row = tid >> 1;
    const int hh  = tid & 1;
    const int m = m0 + row;
    const float* srow = &stage[row * STAGE_PITCH + hh * 64];
    if (MODE == 0) {
        const float pos = (float)(m & (S_ - 1));
        float vb[64], rb[64];
        #pragma unroll
        for (int d = 0; d < 32; d++) {
            const float qlo = srow[d];
            const float qhi = srow[d + 32];
            const float inv = exp2f((float)d * -0.41524101186920654f);
            float sn, cs;
            sincosf(pos * inv, &sn, &cs);
            vb[d] = qlo;      vb[d + 32] = qhi;
            rb[d] = qlo * cs - qhi * sn;
            rb[d + 32] = qhi * cs + qlo * sn;
        }
        const size_t base = (size_t)m * HID_ + n0 + hh * 64;
        #pragma unroll
        for (int q = 0; q < 8; q++) {
            __nv_bfloat162 kh4[4], kl4[4], vh4[4], vl4[4];
            #pragma unroll
            for (int e = 0; e < 4; e++) {
                float v0 = vb[q * 8 + 2 * e], v1 = vb[q * 8 + 2 * e + 1];
                float r0 = rb[q * 8 + 2 * e], r1 = rb[q * 8 + 2 * e + 1];
                __nv_bfloat16 vh0 = bhi(v0), vh1 = bhi(v1);
                __nv_bfloat16 rh0 = bhi(r0), rh1 = bhi(r1);
                vh4[e] = __nv_bfloat162(vh0, vh1);
                vl4[e] = __nv_bfloat162(bhi(v0 - __bfloat162float(vh0)),
                                        bhi(v1 - __bfloat162float(vh1)));
                kh4[e] = __nv_bfloat162(rh0, rh1);
                kl4[e] = __nv_bfloat162(bhi(r0 - __bfloat162float(rh0)),
                                        bhi(r1 - __bfloat162float(rh1)));
            }
            *(int4*)(gKh + base + q * 8) = *(int4*)kh4;
            *(int4*)(gKl + base + q * 8) = *(int4*)kl4;
            *(int4*)(gVh + base + q * 8) = *(int4*)vh4;
            *(int4*)(gVl + base + q * 8) = *(int4*)vl4;
        }
    } else {
        float* op = &out[(size_t)m * HID_ + n0 + hh * 64];
        #pragma unroll
        for (int q = 0; q < 16; q++) {
            float4 f = make_float4(srow[q * 4], srow[q * 4 + 1],
                                   srow[q * 4 + 2], srow[q * 4 + 3]);
            *(float4*)(op + q * 4) = f;
        }
    }
}

// ---------------------------------------------------------------------------
// HMMA sliding-window attention (round-10 core). Epilogue now writes bf16
// splits directly to gAh/gAl (feeds gemm<1>) — no fp32 g_attn round-trip.
// ---------------------------------------------------------------------------
#define QH_OFF  0
#define QL_OFF  8192
#define KVH_OFF 16384
#define KVL_OFF 24576
#define PH_OFF  32768
#define PL_OFF  58368
#define RED_OFF 83968
#define AT_SMEM 84992
#define P_PITCH 400

__global__ __launch_bounds__(256, 2)
void attn_mma() {
    extern __shared__ __align__(1024) char sm[];
    const uint32_t smb = smem_u32(sm);

    const int t0 = blockIdx.x * 64;
    const int bh = blockIdx.y;
    const int b = bh / NH_, h = bh % NH_;
    const int tid = threadIdx.x;
    const int wid = tid >> 5, lane = tid & 31;
    const int wm2 = (wid >> 2) * 32;
    const int wg  = wid & 3;
    const int wn2 = wg * 16;

    const int arow = lane & 15;
    const int ahalf = (lane >> 4) << 4;
    const int brow = lane & 7;
    const int bhalf = ((lane >> 3) & 1) << 4;

    float* red = (float*)(sm + RED_OFF);

    #pragma unroll
    for (int t = 0; t < 2; t++) {
        const int seg = tid + t * 256;
        const int row = seg >> 3, sc = seg & 7;
        const size_t g = ((size_t)(b * S_ + t0 + row)) * HID_ + h * 64 + sc * 8;
        const uint32_t off = SWZ128((uint32_t)(row * 128 + sc * 16));
        *(int4*)(sm + QH_OFF + off) = *(const int4*)(gKh + g);
        *(int4*)(sm + QL_OFF + off) = *(const int4*)(gKl + g);
    }

    float sacc[3][2][2][4] = {};
    for (int kc = 0; kc < 3; kc++) {
        const int s0 = t0 - 64 + kc * 64;
        __syncthreads();
        #pragma unroll
        for (int t = 0; t < 2; t++) {
            const int seg = tid + t * 256;
            const int row = seg >> 3, sc = seg & 7;
            const int s = s0 + row;
            int4 vh = make_int4(0, 0, 0, 0), vl = make_int4(0, 0, 0, 0);
            if ((unsigned)s < (unsigned)S_) {
                const size_t g = ((size_t)(b * S_ + s)) * HID_ + h * 64 + sc * 8;
                vh = *(const int4*)(gKh + g);
                vl = *(const int4*)(gKl + g);
            }
            const uint32_t off = SWZ128((uint32_t)(row * 128 + sc * 16));
            *(int4*)(sm + KVH_OFF + off) = vh;
            *(int4*)(sm + KVL_OFF + off) = vl;
        }
        __syncthreads();

        #pragma unroll
        for (int ks = 0; ks < 4; ks++) {
            const int kb = ks * 32;
            uint32_t qh_[2][4], ql_[2][4], kh_[2][2], kl_[2][2];
            #pragma unroll
            for (int mt = 0; mt < 2; mt++) {
                const uint32_t ao = SWZ128((wm2 + mt * 16 + arow) * 128 + kb + ahalf);
                ldmx4(qh_[mt], smb + QH_OFF + ao);
                ldmx4(ql_[mt], smb + QL_OFF + ao);
            }
            #pragma unroll
            for (int nt = 0; nt < 2; nt++) {
                const uint32_t bo = SWZ128((wn2 + nt * 8 + brow) * 128 + kb + bhalf);
                ldmx2(kh_[nt], smb + KVH_OFF + bo);
                ldmx2(kl_[nt], smb + KVL_OFF + bo);
            }
            #pragma unroll
            for (int mt = 0; mt < 2; mt++)
                #pragma unroll
                for (int nt = 0; nt < 2; nt++) {
                    mma_bf16(sacc[kc][mt][nt], qh_[mt], kh_[nt]);
                    mma_bf16(sacc[kc][mt][nt], qh_[mt], kl_[nt]);
                    mma_bf16(sacc[kc][mt][nt], ql_[mt], kh_[nt]);
                }
        }
    }

    #pragma unroll
    for (int kc = 0; kc < 3; kc++)
        #pragma unroll
        for (int mt = 0; mt < 2; mt++)
            #pragma unroll
            for (int nt = 0; nt < 2; nt++)
                #pragma unroll
                for (int j = 0; j < 4; j++) {
                    const int row = wm2 + mt * 16 + (lane >> 2) + (j >> 1) * 8;
                    const int col = kc * 64 + wn2 + nt * 8 + 2 * (lane & 3) + (j & 1);
                    const int t = t0 + row;
                    const int s = t0 - 64 + col;
                    int dist = t - s; if (dist < 0) dist = -dist;
                    const bool valid = ((unsigned)s < (unsigned)S_) && (dist <= WHALF);
                    sacc[kc][mt][nt][j] = valid ? sacc[kc][mt][nt][j] * 0.125f : -1e30f;
                }

    float rmax[2][2];
    #pragma unroll
    for (int mt = 0; mt < 2; mt++)
        #pragma unroll
        for (int hf = 0; hf < 2; hf++) {
            float m = -1e30f;
            #pragma unroll
            for (int kc = 0; kc < 3; kc++)
                #pragma unroll
                for (int nt = 0; nt < 2; nt++) {
                    m = fmaxf(m, sacc[kc][mt][nt][hf * 2]);
                    m = fmaxf(m, sacc[kc][mt][nt][hf * 2 + 1]);
                }
            m = fmaxf(m, __shfl_xor_sync(0xffffffffu, m, 1));
            m = fmaxf(m, __shfl_xor_sync(0xffffffffu, m, 2));
            rmax[mt][hf] = m;
        }
    #pragma unroll
    for (int mt = 0; mt < 2; mt++)
        #pragma unroll
        for (int hf = 0; hf < 2; hf++)
            red[(wm2 + mt * 16 + (lane >> 2) + hf * 8) * 4 + wg] = rmax[mt][hf];
    __syncthreads();
    #pragma unroll
    for (int mt = 0; mt < 2; mt++)
        #pragma unroll
        for (int hf = 0; hf < 2; hf++) {
            const int r = wm2 + mt * 16 + (lane >> 2) + hf * 8;
            rmax[mt][hf] = fmaxf(fmaxf(red[r * 4], red[r * 4 + 1]),
                                 fmaxf(red[r * 4 + 2], red[r * 4 + 3]));
        }
    __syncthreads();

    float rsum[2][2];
    #pragma unroll
    for (int mt = 0; mt < 2; mt++)
        #pragma unroll
        for (int hf = 0; hf < 2; hf++) {
            float s = 0.0f;
            #pragma unroll
            for (int kc = 0; kc < 3; kc++)
                #pragma unroll
                for (int nt = 0; nt < 2; nt++)
                    #pragma unroll
                    for (int e = 0; e < 2; e++) {
                        float p = __expf(sacc[kc][mt][nt][hf * 2 + e] - rmax[mt][hf]);
                        sacc[kc][mt][nt][hf * 2 + e] = p;
                        s += p;
                    }
            s += __shfl_xor_sync(0xffffffffu, s, 1);
            s += __shfl_xor_sync(0xffffffffu, s, 2);
            rsum[mt][hf] = s;
        }
    #pragma unroll
    for (int mt = 0; mt < 2; mt++)
        #pragma unroll
        for (int hf = 0; hf < 2; hf++)
            red[(wm2 + mt * 16 + (lane >> 2) + hf * 8) * 4 + wg] = rsum[mt][hf];
    __syncthreads();
    #pragma unroll
    for (int mt = 0; mt < 2; mt++)
        #pragma unroll
        for (int hf = 0; hf < 2; hf++) {
            const int r = wm2 + mt * 16 + (lane >> 2) + hf * 8;
            rsum[mt][hf] = 1.0f / (red[r * 4] + red[r * 4 + 1] +
                                   red[r * 4 + 2] + red[r * 4 + 3]);
        }

    #pragma unroll
    for (int kc = 0; kc < 3; kc++)
        #pragma unroll
        for (int mt = 0; mt < 2; mt++)
            #pragma unroll
            for (int nt = 0; nt < 2; nt++)
                #pragma unroll
                for (int hf = 0; hf < 2; hf++) {
                    const int row = wm2 + mt * 16 + (lane >> 2) + hf * 8;
                    const int col = kc * 64 + wn2 + nt * 8 + 2 * (lane & 3);
                    float p0 = sacc[kc][mt][nt][hf * 2]     * rsum[mt][hf];
                    float p1 = sacc[kc][mt][nt][hf * 2 + 1] * rsum[mt][hf];
                    __nv_bfloat16 h0 = bhi(p0), h1 = bhi(p1);
                    __nv_bfloat162 ph2(h0, h1);
                    __nv_bfloat162 pl2(bhi(p0 - __bfloat162float(h0)),
                                       bhi(p1 - __bfloat162float(h1)));
                    *(__nv_bfloat162*)(sm + PH_OFF + row * P_PITCH + col * 2) = ph2;
                    *(__nv_bfloat162*)(sm + PL_OFF + row * P_PITCH + col * 2) = pl2;
                }

    const int wn2v = wg * 16;
    float oacc[2][2][4] = {};
    for (int kc = 0; kc < 3; kc++) {
        const int s0 = t0 - 64 + kc * 64;
        __syncthreads();
        #pragma unroll
        for (int t = 0; t < 2; t++) {
            const int seg = tid + t * 256;
            const int row = seg >> 3, sc = seg & 7;
            const int s = s0 + row;
            int4 vh = make_int4(0, 0, 0, 0), vl = make_int4(0, 0, 0, 0);
            if ((unsigned)s < (unsigned)S_) {
                const size_t g = ((size_t)(b * S_ + s)) * HID_ + h * 64 + sc * 8;
                vh = *(const int4*)(gVh + g);
                vl = *(const int4*)(gVl + g);
            }
            const uint32_t off = SWZ128((uint32_t)(row * 128 + sc * 16));
            *(int4*)(sm + KVH_OFF + off) = vh;
            *(int4*)(sm + KVL_OFF + off) = vl;
        }
        __syncthreads();

        #pragma unroll
        for (int ks = 0; ks < 4; ks++) {
            uint32_t pa_h[2][4], pa_l[2][4], vh_[2][2], vl_[2][2];
            #pragma unroll
            for (int mt = 0; mt < 2; mt++) {
                const uint32_t ao = (uint32_t)((wm2 + mt * 16 + arow) * P_PITCH
                                               + kc * 128 + ks * 32 + ahalf);
                ldmx4(pa_h[mt], smb + PH_OFF + ao);
                ldmx4(pa_l[mt], smb + PL_OFF + ao);
            }
            const int krow = ks * 16 + arow;
            #pragma unroll
            for (int nt = 0; nt < 2; nt++) {
                const uint32_t bo = SWZ128((uint32_t)(krow * 128
                                           + (wn2v + nt * 8) * 2));
                ldmx2t(vh_[nt], smb + KVH_OFF + bo);
                ldmx2t(vl_[nt], smb + KVL_OFF + bo);
            }
            #pragma unroll
            for (int mt = 0; mt < 2; mt++)
                #pragma unroll
                for (int nt = 0; nt < 2; nt++) {
                    mma_bf16(oacc[mt][nt], pa_h[mt], vh_[nt]);
                    mma_bf16(oacc[mt][nt], pa_h[mt], vl_[nt]);
                    mma_bf16(oacc[mt][nt], pa_l[mt], vh_[nt]);
                }
        }
    }

    // ---- epilogue: stage O, then split to bf16 gAh/gAl directly ----
    __syncthreads();
    float* stage = (float*)(sm + PH_OFF);   // [64][68]
    #pragma unroll
    for (int mt = 0; mt < 2; mt++)
        #pragma unroll
        for (int nt = 0; nt < 2; nt++) {
            const int r = wm2 + mt * 16 + (lane >> 2);
            const int c = wn2v + nt * 8 + 2 * (lane & 3);
            *(float2*)&stage[r * 68 + c] = make_float2(oacc[mt][nt][0], oacc[mt][nt][1]);
            *(float2*)&stage[(r + 8) * 68 + c] = make_float2(oacc[mt][nt][2], oacc[mt][nt][3]);
        }
    __syncthreads();
    {
        const int row = tid >> 2, q4 = tid & 3;
        const size_t base = ((size_t)(b * S_ + t0 + row)) * HID_ + h * 64 + q4 * 16;
        const float* sp = &stage[row * 68 + q4 * 16];
        __nv_bfloat162 hbuf[8], lbuf[8];
        #pragma unroll
        for (int e = 0; e < 8; e++) {
            float v0 = sp[2 * e], v1 = sp[2 * e + 1];
            __nv_bfloat16 h0 = bhi(v0), h1 = bhi(v1);
            hbuf[e] = __nv_bfloat162(h0, h1);
            lbuf[e] = __nv_bfloat162(bhi(v0 - __bfloat162float(h0)),
                                     bhi(v1 - __bfloat162float(h1)));
        }
        *(int4*)(gAh + base)     = *(int4*)&hbuf[0];
        *(int4*)(gAh + base + 8) = *(int4*)&hbuf[4];
        *(int4*)(gAl + base)     = *(int4*)&lbuf[0];
        *(int4*)(gAl + base + 8) = *(int4*)&lbuf[4];
    }
}

// ---------------------------------------------------------------------------
extern "C" void kernel_launch(void* const* d_in, const int* in_sizes, int n_in,
                              void* d_out, int out_size) {
    const float* hidden = (const float*)d_in[0];
    const float* Wq     = (const float*)d_in[1];
    const float* Wo     = (const float*)d_in[2];
    float* out = (float*)d_out;
    (void)in_sizes; (void)n_in; (void)out_size;

    cudaFuncSetAttribute(gemm_mma<0>,
                         cudaFuncAttributeMaxDynamicSharedMemorySize, GT_SMEM);
    cudaFuncSetAttribute(gemm_mma<1>,
                         cudaFuncAttributeMaxDynamicSharedMemorySize, GT_SMEM);
    cudaFuncSetAttribute(attn_mma,
                         cudaFuncAttributeMaxDynamicSharedMemorySize, AT_SMEM);

    split_bf16<0><<<(M_ * HID_ / 4 + 255) / 256, 256>>>(hidden, M_ * HID_);
    split_bf16<1><<<(HID_ * HID_ / 4 + 255) / 256, 256>>>(Wq, HID_ * HID_);
    split_bf16<2><<<(HID_ * HID_ / 4 + 255) / 256, 256>>>(Wo, HID_ * HID_);

    dim3 gemm_grid(HID_ / 128, M_ / 128);
    gemm_mma<0><<<gemm_grid, 256, GT_SMEM>>>(nullptr);

    dim3 attn_grid(S_ / 64, B_ * NH_);
    attn_mma<<<attn_grid, 256, AT_SMEM>>>();   // writes gAh/gAl for gemm<1>

    gemm_mma<1><<<gemm_grid, 256, GT_SMEM>>>(out);
}

// round 12
// speedup vs baseline: 3.6340x; 1.2552x over previous
#include <cuda_runtime.h>
#include <cuda_bf16.h>
#include <cuda_fp16.h>
#include <math.h>
#include <stdint.h>

#define B_    2
#define S_    2048
#define HID_  768
#define NH_   12
#define HD_   64
#define M_    (B_ * S_)          // 4096 rows
#define WHALF 64                 // WINDOW/2

// ---------------- device scratch (no allocations allowed) ------------------
// fp16 operands for projection GEMMs (2-term scheme: A hi only, W hi+lo)
__device__ __align__(16) __half gAh[M_ * HID_];
__device__ __align__(16) __half gW1h[HID_ * HID_];
__device__ __align__(16) __half gW1l[HID_ * HID_];
__device__ __align__(16) __half gW2h[HID_ * HID_];
__device__ __align__(16) __half gW2l[HID_ * HID_];

// bf16 splits for attention (3-term, written by gemm<0> epilogue)
__device__ __align__(16) __nv_bfloat16 gKh[M_ * HID_];  // q_rot hi (= k)
__device__ __align__(16) __nv_bfloat16 gKl[M_ * HID_];  // q_rot lo
__device__ __align__(16) __nv_bfloat16 gVh[M_ * HID_];  // v hi
__device__ __align__(16) __nv_bfloat16 gVl[M_ * HID_];  // v lo

// ---------------- PTX helpers (baseline ISA only) --------------------------
__device__ __forceinline__ uint32_t smem_u32(const void* p) {
    uint32_t a;
    asm("{ .reg .u64 t; cvta.to.shared.u64 t, %1; cvt.u32.u64 %0, t; }"
        : "=r"(a) : "l"(p));
    return a;
}
__device__ __forceinline__ void ldmx4(uint32_t r[4], uint32_t addr) {
    asm volatile("ldmatrix.sync.aligned.m8n8.x4.shared.b16 {%0,%1,%2,%3}, [%4];"
                 : "=r"(r[0]), "=r"(r[1]), "=r"(r[2]), "=r"(r[3]) : "r"(addr));
}
__device__ __forceinline__ void ldmx2(uint32_t r[2], uint32_t addr) {
    asm volatile("ldmatrix.sync.aligned.m8n8.x2.shared.b16 {%0,%1}, [%2];"
                 : "=r"(r[0]), "=r"(r[1]) : "r"(addr));
}
__device__ __forceinline__ void ldmx2t(uint32_t r[2], uint32_t addr) {
    asm volatile("ldmatrix.sync.aligned.m8n8.x2.trans.shared.b16 {%0,%1}, [%2];"
                 : "=r"(r[0]), "=r"(r[1]) : "r"(addr));
}
__device__ __forceinline__ void mma_bf16(float c[4], const uint32_t a[4],
                                         const uint32_t b[2]) {
    asm volatile(
        "mma.sync.aligned.m16n8k16.row.col.f32.bf16.bf16.f32 "
        "{%0,%1,%2,%3}, {%4,%5,%6,%7}, {%8,%9}, {%0,%1,%2,%3};"
        : "+f"(c[0]), "+f"(c[1]), "+f"(c[2]), "+f"(c[3])
        : "r"(a[0]), "r"(a[1]), "r"(a[2]), "r"(a[3]), "r"(b[0]), "r"(b[1]));
}
__device__ __forceinline__ void mma_f16(float c[4], const uint32_t a[4],
                                        const uint32_t b[2]) {
    asm volatile(
        "mma.sync.aligned.m16n8k16.row.col.f32.f16.f16.f32 "
        "{%0,%1,%2,%3}, {%4,%5,%6,%7}, {%8,%9}, {%0,%1,%2,%3};"
        : "+f"(c[0]), "+f"(c[1]), "+f"(c[2]), "+f"(c[3])
        : "r"(a[0]), "r"(a[1]), "r"(a[2]), "r"(a[3]), "r"(b[0]), "r"(b[1]));
}
__device__ __forceinline__ void cp16(uint32_t dst, const void* src) {
    asm volatile("cp.async.cg.shared.global [%0], [%1], 16;"
                 :: "r"(dst), "l"(src));
}
#define CP_COMMIT() asm volatile("cp.async.commit_group;" ::: "memory")
#define CP_WAIT1()  asm volatile("cp.async.wait_group 1;" ::: "memory")

#define SWZ64(off)  ((off) ^ (((off) >> 3) & 0x30))
#define SWZ128(off) ((off) ^ (((off) >> 3) & 0x70))

__device__ __forceinline__ __nv_bfloat16 bhi(float x) { return __float2bfloat16(x); }

// ---------------------------------------------------------------------------
// fp16 split converts. DST: 0 = gAh (hi only), 1 = gW1 (hi+lo), 2 = gW2.
// Device symbols selected in device code only.
// ---------------------------------------------------------------------------
template<int DST>
__global__ __launch_bounds__(256)
void split_f16(const float* __restrict__ src, int n) {
    __half* __restrict__ hi = (DST == 0) ? gAh : (DST == 1) ? gW1h : gW2h;
    __half* __restrict__ lo = (DST == 2) ? gW2l : gW1l;
    int i = (blockIdx.x * 256 + threadIdx.x) * 4;
    if (i >= n) return;
    float4 v = *(const float4*)(src + i);
    __half h0 = __float2half(v.x), h1 = __float2half(v.y);
    __half h2 = __float2half(v.z), h3 = __float2half(v.w);
    *(__half2*)(hi + i)     = __half2(h0, h1);
    *(__half2*)(hi + i + 2) = __half2(h2, h3);
    if (DST != 0) {
        __half l0 = __float2half(v.x - __half2float(h0));
        __half l1 = __float2half(v.y - __half2float(h1));
        __half l2 = __float2half(v.z - __half2float(h2));
        __half l3 = __float2half(v.w - __half2float(h3));
        *(__half2*)(lo + i)     = __half2(l0, l1);
        *(__half2*)(lo + i + 2) = __half2(l2, l3);
    }
}

// ---------------------------------------------------------------------------
// Pipelined HMMA GEMM, fp16 2-term: C = Ah*Wh + Ah*Wl.
// CTA tile 128x128, K chunks of 32, 3-stage cp.async pipeline.
// 8 warps 2(m)x4(n), warp tile 64x32.  3 tiles per stage: Ah, Wh, Wl.
// MODE 0: epilogue = RoPE + bf16 splits -> gKh/gKl, gVh/gVl.
// MODE 1: epilogue = fp32 store to out.
// ---------------------------------------------------------------------------
#define TILE_B   8192
#define STAGE_B  (3 * TILE_B)               // 24576
#define STAGE_PITCH 132
#define GT_SMEM (1024 + 3 * STAGE_B)        // 74752; epi overlay 67584 fits
#define NCHUNK (HID_ / 32)                  // 24

template<int MODE>
__global__ __launch_bounds__(256, 2)
void gemm_mma(float* __restrict__ out) {
    extern __shared__ __align__(1024) char sm[];
    const uint32_t smb = smem_u32(sm);

    const int n0 = blockIdx.x * 128;
    const int m0 = blockIdx.y * 128;
    const int tid = threadIdx.x;
    const int wid = tid >> 5, lane = tid & 31;
    const int wm = (wid >> 2) * 64;
    const int wn = (wid & 3) * 32;

    const __half* __restrict__ Bh = (MODE == 0) ? gW1h : gW2h;
    const __half* __restrict__ Bl = (MODE == 0) ? gW1l : gW2l;

    const int lrow0 = tid >> 2;
    const int lseg  = tid & 3;
    const size_t gA0 = (size_t)(m0 + lrow0) * HID_ + lseg * 8;
    const size_t gA1 = (size_t)(m0 + lrow0 + 64) * HID_ + lseg * 8;
    const size_t gW0 = (size_t)(n0 + lrow0) * HID_ + lseg * 8;
    const size_t gW1v = (size_t)(n0 + lrow0 + 64) * HID_ + lseg * 8;
    const uint32_t so0 = SWZ64((uint32_t)(lrow0 * 64 + lseg * 16));
    const uint32_t so1 = SWZ64((uint32_t)((lrow0 + 64) * 64 + lseg * 16));

    #define LOAD_CHUNK(cc, st)                                                \
    {                                                                         \
        const int k0_ = (cc) * 32;                                            \
        const uint32_t s_ = smb + 1024 + (st) * STAGE_B;                      \
        cp16(s_ + so0,              gAh + gA0 + k0_);                         \
        cp16(s_ + so1,              gAh + gA1 + k0_);                         \
        cp16(s_ + TILE_B + so0,     Bh + gW0 + k0_);                          \
        cp16(s_ + TILE_B + so1,     Bh + gW1v + k0_);                         \
        cp16(s_ + 2 * TILE_B + so0, Bl + gW0 + k0_);                          \
        cp16(s_ + 2 * TILE_B + so1, Bl + gW1v + k0_);                         \
    }

    float acc[4][4][4] = {};
    const int arow = lane & 15;
    const int ahalf = (lane >> 4) << 4;
    const int brow = lane & 7;
    const int bhalf = ((lane >> 3) & 1) << 4;

    LOAD_CHUNK(0, 0); CP_COMMIT();
    LOAD_CHUNK(1, 1); CP_COMMIT();

    int st = 0;
    for (int c = 0; c < NCHUNK; c++) {
        const uint32_t uA  = smb + 1024 + st * STAGE_B;
        const uint32_t uWh = uA + TILE_B;
        const uint32_t uWl = uA + 2 * TILE_B;

        CP_WAIT1();
        __syncthreads();

        if (c + 2 < NCHUNK) {
            const int st2 = (st + 2) % 3;
            LOAD_CHUNK(c + 2, st2);
        }
        CP_COMMIT();

        #pragma unroll
        for (int ks = 0; ks < 2; ks++) {
            const int kb = ks * 32;
            uint32_t ah[4][4], bh2[4][2], bl2[4][2];
            #pragma unroll
            for (int mt = 0; mt < 4; mt++) {
                const int r = wm + mt * 16 + arow;
                ldmx4(ah[mt], uA + SWZ64(r * 64 + kb + ahalf));
            }
            #pragma unroll
            for (int nt = 0; nt < 4; nt++) {
                const int r = wn + nt * 8 + brow;
                const uint32_t off = SWZ64(r * 64 + kb + bhalf);
                ldmx2(bh2[nt], uWh + off);
                ldmx2(bl2[nt], uWl + off);
            }
            #pragma unroll
            for (int mt = 0; mt < 4; mt++)
                #pragma unroll
                for (int nt = 0; nt < 4; nt++)
                    mma_f16(acc[mt][nt], ah[mt], bh2[nt]);
            #pragma unroll
            for (int mt = 0; mt < 4; mt++)
                #pragma unroll
                for (int nt = 0; nt < 4; nt++)
                    mma_f16(acc[mt][nt], ah[mt], bl2[nt]);
        }
        st = (st + 1) % 3;
    }
    #undef LOAD_CHUNK
    __syncthreads();

    // ---- epilogue: stage in smem, then coalesced processing ----
    float* stage = (float*)sm;
    #pragma unroll
    for (int mt = 0; mt < 4; mt++)
        #pragma unroll
        for (int nt = 0; nt < 4; nt++) {
            const int r = wm + mt * 16 + (lane >> 2);
            const int cc = wn + nt * 8 + 2 * (lane & 3);
            *(float2*)&stage[r * STAGE_PITCH + cc] =
                make_float2(acc[mt][nt][0], acc[mt][nt][1]);
            *(float2*)&stage[(r + 8) * STAGE_PITCH + cc] =
                make_float2(acc[mt][nt][2], acc[mt][nt][3]);
        }
    __syncthreads();

    const int row = tid >> 1;
    const int hh  = tid & 1;
    const int m = m0 + row;
    const float* srow = &stage[row * STAGE_PITCH + hh * 64];
    if (MODE == 0) {
        const float pos = (float)(m & (S_ - 1));
        float vb[64], rb[64];
        #pragma unroll
        for (int d = 0; d < 32; d++) {
            const float qlo = srow[d];
            const float qhi = srow[d + 32];
            const float inv = exp2f((float)d * -0.41524101186920654f);
            float sn, cs;
            sincosf(pos * inv, &sn, &cs);
            vb[d] = qlo;      vb[d + 32] = qhi;
            rb[d] = qlo * cs - qhi * sn;
            rb[d + 32] = qhi * cs + qlo * sn;
        }
        const size_t base = (size_t)m * HID_ + n0 + hh * 64;
        #pragma unroll
        for (int q = 0; q < 8; q++) {
            __nv_bfloat162 kh4[4], kl4[4], vh4[4], vl4[4];
            #pragma unroll
            for (int e = 0; e < 4; e++) {
                float v0 = vb[q * 8 + 2 * e], v1 = vb[q * 8 + 2 * e + 1];
                float r0 = rb[q * 8 + 2 * e], r1 = rb[q * 8 + 2 * e + 1];
                __nv_bfloat16 vh0 = bhi(v0), vh1 = bhi(v1);
                __nv_bfloat16 rh0 = bhi(r0), rh1 = bhi(r1);
                vh4[e] = __nv_bfloat162(vh0, vh1);
                vl4[e] = __nv_bfloat162(bhi(v0 - __bfloat162float(vh0)),
                                        bhi(v1 - __bfloat162float(vh1)));
                kh4[e] = __nv_bfloat162(rh0, rh1);
                kl4[e] = __nv_bfloat162(bhi(r0 - __bfloat162float(rh0)),
                                        bhi(r1 - __bfloat162float(rh1)));
            }
            *(int4*)(gKh + base + q * 8) = *(int4*)kh4;
            *(int4*)(gKl + base + q * 8) = *(int4*)kl4;
            *(int4*)(gVh + base + q * 8) = *(int4*)vh4;
            *(int4*)(gVl + base + q * 8) = *(int4*)vl4;
        }
    } else {
        float* op = &out[(size_t)m * HID_ + n0 + hh * 64];
        #pragma unroll
        for (int q = 0; q < 16; q++) {
            float4 f = make_float4(srow[q * 4], srow[q * 4 + 1],
                                   srow[q * 4 + 2], srow[q * 4 + 3]);
            *(float4*)(op + q * 4) = f;
        }
    }
}

// ---------------------------------------------------------------------------
// HMMA sliding-window attention (3-term bf16, unchanged core). Epilogue
// writes fp16 hi only -> gAh (gemm<1> is 2-term on the A side).
// ---------------------------------------------------------------------------
#define QH_OFF  0
#define QL_OFF  8192
#define KVH_OFF 16384
#define KVL_OFF 24576
#define PH_OFF  32768
#define PL_OFF  58368
#define RED_OFF 83968
#define AT_SMEM 84992
#define P_PITCH 400

__global__ __launch_bounds__(256, 2)
void attn_mma() {
    extern __shared__ __align__(1024) char sm[];
    const uint32_t smb = smem_u32(sm);

    const int t0 = blockIdx.x * 64;
    const int bh = blockIdx.y;
    const int b = bh / NH_, h = bh % NH_;
    const int tid = threadIdx.x;
    const int wid = tid >> 5, lane = tid & 31;
    const int wm2 = (wid >> 2) * 32;
    const int wg  = wid & 3;
    const int wn2 = wg * 16;

    const int arow = lane & 15;
    const int ahalf = (lane >> 4) << 4;
    const int brow = lane & 7;
    const int bhalf = ((lane >> 3) & 1) << 4;

    float* red = (float*)(sm + RED_OFF);

    #pragma unroll
    for (int t = 0; t < 2; t++) {
        const int seg = tid + t * 256;
        const int row = seg >> 3, sc = seg & 7;
        const size_t g = ((size_t)(b * S_ + t0 + row)) * HID_ + h * 64 + sc * 8;
        const uint32_t off = SWZ128((uint32_t)(row * 128 + sc * 16));
        *(int4*)(sm + QH_OFF + off) = *(const int4*)(gKh + g);
        *(int4*)(sm + QL_OFF + off) = *(const int4*)(gKl + g);
    }

    float sacc[3][2][2][4] = {};
    for (int kc = 0; kc < 3; kc++) {
        const int s0 = t0 - 64 + kc * 64;
        __syncthreads();
        #pragma unroll
        for (int t = 0; t < 2; t++) {
            const int seg = tid + t * 256;
            const int row = seg >> 3, sc = seg & 7;
            const int s = s0 + row;
            int4 vh = make_int4(0, 0, 0, 0), vl = make_int4(0, 0, 0, 0);
            if ((unsigned)s < (unsigned)S_) {
                const size_t g = ((size_t)(b * S_ + s)) * HID_ + h * 64 + sc * 8;
                vh = *(const int4*)(gKh + g);
                vl = *(const int4*)(gKl + g);
            }
            const uint32_t off = SWZ128((uint32_t)(row * 128 + sc * 16));
            *(int4*)(sm + KVH_OFF + off) = vh;
            *(int4*)(sm + KVL_OFF + off) = vl;
        }
        __syncthreads();

        #pragma unroll
        for (int ks = 0; ks < 4; ks++) {
            const int kb = ks * 32;
            uint32_t qh_[2][4], ql_[2][4], kh_[2][2], kl_[2][2];
            #pragma unroll
            for (int mt = 0; mt < 2; mt++) {
                const uint32_t ao = SWZ128((wm2 + mt * 16 + arow) * 128 + kb + ahalf);
                ldmx4(qh_[mt], smb + QH_OFF + ao);
                ldmx4(ql_[mt], smb + QL_OFF + ao);
            }
            #pragma unroll
            for (int nt = 0; nt < 2; nt++) {
                const uint32_t bo = SWZ128((wn2 + nt * 8 + brow) * 128 + kb + bhalf);
                ldmx2(kh_[nt], smb + KVH_OFF + bo);
                ldmx2(kl_[nt], smb + KVL_OFF + bo);
            }
            #pragma unroll
            for (int mt = 0; mt < 2; mt++)
                #pragma unroll
                for (int nt = 0; nt < 2; nt++) {
                    mma_bf16(sacc[kc][mt][nt], qh_[mt], kh_[nt]);
                    mma_bf16(sacc[kc][mt][nt], qh_[mt], kl_[nt]);
                    mma_bf16(sacc[kc][mt][nt], ql_[mt], kh_[nt]);
                }
        }
    }

    #pragma unroll
    for (int kc = 0; kc < 3; kc++)
        #pragma unroll
        for (int mt = 0; mt < 2; mt++)
            #pragma unroll
            for (int nt = 0; nt < 2; nt++)
                #pragma unroll
                for (int j = 0; j < 4; j++) {
                    const int row = wm2 + mt * 16 + (lane >> 2) + (j >> 1) * 8;
                    const int col = kc * 64 + wn2 + nt * 8 + 2 * (lane & 3) + (j & 1);
                    const int t = t0 + row;
                    const int s = t0 - 64 + col;
                    int dist = t - s; if (dist < 0) dist = -dist;
                    const bool valid = ((unsigned)s < (unsigned)S_) && (dist <= WHALF);
                    sacc[kc][mt][nt][j] = valid ? sacc[kc][mt][nt][j] * 0.125f : -1e30f;
                }

    float rmax[2][2];
    #pragma unroll
    for (int mt = 0; mt < 2; mt++)
        #pragma unroll
        for (int hf = 0; hf < 2; hf++) {
            float m = -1e30f;
            #pragma unroll
            for (int kc = 0; kc < 3; kc++)
                #pragma unroll
                for (int nt = 0; nt < 2; nt++) {
                    m = fmaxf(m, sacc[kc][mt][nt][hf * 2]);
                    m = fmaxf(m, sacc[kc][mt][nt][hf * 2 + 1]);
                }
            m = fmaxf(m, __shfl_xor_sync(0xffffffffu, m, 1));
            m = fmaxf(m, __shfl_xor_sync(0xffffffffu, m, 2));
            rmax[mt][hf] = m;
        }
    #pragma unroll
    for (int mt = 0; mt < 2; mt++)
        #pragma unroll
        for (int hf = 0; hf < 2; hf++)
            red[(wm2 + mt * 16 + (lane >> 2) + hf * 8) * 4 + wg] = rmax[mt][hf];
    __syncthreads();
    #pragma unroll
    for (int mt = 0; mt < 2; mt++)
        #pragma unroll
        for (int hf = 0; hf < 2; hf++) {
            const int r = wm2 + mt * 16 + (lane >> 2) + hf * 8;
            rmax[mt][hf] = fmaxf(fmaxf(red[r * 4], red[r * 4 + 1]),
                                 fmaxf(red[r * 4 + 2], red[r * 4 + 3]));
        }
    __syncthreads();

    float rsum[2][2];
    #pragma unroll
    for (int mt = 0; mt < 2; mt++)
        #pragma unroll
        for (int hf = 0; hf < 2; hf++) {
            float s = 0.0f;
            #pragma unroll
            for (int kc = 0; kc < 3; kc++)
                #pragma unroll
                for (int nt = 0; nt < 2; nt++)
                    #pragma unroll
                    for (int e = 0; e < 2; e++) {
                        float p = __expf(sacc[kc][mt][nt][hf * 2 + e] - rmax[mt][hf]);
                        sacc[kc][mt][nt][hf * 2 + e] = p;
                        s += p;
                    }
            s += __shfl_xor_sync(0xffffffffu, s, 1);
            s += __shfl_xor_sync(0xffffffffu, s, 2);
            rsum[mt][hf] = s;
        }
    #pragma unroll
    for (int mt = 0; mt < 2; mt++)
        #pragma unroll
        for (int hf = 0; hf < 2; hf++)
            red[(wm2 + mt * 16 + (lane >> 2) + hf * 8) * 4 + wg] = rsum[mt][hf];
    __syncthreads();
    #pragma unroll
    for (int mt = 0; mt < 2; mt++)
        #pragma unroll
        for (int hf = 0; hf < 2; hf++) {
            const int r = wm2 + mt * 16 + (lane >> 2) + hf * 8;
            rsum[mt][hf] = 1.0f / (red[r * 4] + red[r * 4 + 1] +
                                   red[r * 4 + 2] + red[r * 4 + 3]);
        }

    #pragma unroll
    for (int kc = 0; kc < 3; kc++)
        #pragma unroll
        for (int mt = 0; mt < 2; mt++)
            #pragma unroll
            for (int nt = 0; nt < 2; nt++)
                #pragma unroll
                for (int hf = 0; hf < 2; hf++) {
                    const int row = wm2 + mt * 16 + (lane >> 2) + hf * 8;
                    const int col = kc * 64 + wn2 + nt * 8 + 2 * (lane & 3);
                    float p0 = sacc[kc][mt][nt][hf * 2]     * rsum[mt][hf];
                    float p1 = sacc[kc][mt][nt][hf * 2 + 1] * rsum[mt][hf];
                    __nv_bfloat16 h0 = bhi(p0), h1 = bhi(p1);
                    __nv_bfloat162 ph2(h0, h1);
                    __nv_bfloat162 pl2(bhi(p0 - __bfloat162float(h0)),
                                       bhi(p1 - __bfloat162float(h1)));
                    *(__nv_bfloat162*)(sm + PH_OFF + row * P_PITCH + col * 2) = ph2;
                    *(__nv_bfloat162*)(sm + PL_OFF + row * P_PITCH + col * 2) = pl2;
                }

    const int wn2v = wg * 16;
    float oacc[2][2][4] = {};
    for (int kc = 0; kc < 3; kc++) {
        const int s0 = t0 - 64 + kc * 64;
        __syncthreads();
        #pragma unroll
        for (int t = 0; t < 2; t++) {
            const int seg = tid + t * 256;
            const int row = seg >> 3, sc = seg & 7;
            const int s = s0 + row;
            int4 vh = make_int4(0, 0, 0, 0), vl = make_int4(0, 0, 0, 0);
            if ((unsigned)s < (unsigned)S_) {
                const size_t g = ((size_t)(b * S_ + s)) * HID_ + h * 64 + sc * 8;
                vh = *(const int4*)(gVh + g);
                vl = *(const int4*)(gVl + g);
            }
            const uint32_t off = SWZ128((uint32_t)(row * 128 + sc * 16));
            *(int4*)(sm + KVH_OFF + off) = vh;
            *(int4*)(sm + KVL_OFF + off) = vl;
        }
        __syncthreads();

        #pragma unroll
        for (int ks = 0; ks < 4; ks++) {
            uint32_t pa_h[2][4], pa_l[2][4], vh_[2][2], vl_[2][2];
            #pragma unroll
            for (int mt = 0; mt < 2; mt++) {
                const uint32_t ao = (uint32_t)((wm2 + mt * 16 + arow) * P_PITCH
                                               + kc * 128 + ks * 32 + ahalf);
                ldmx4(pa_h[mt], smb + PH_OFF + ao);
                ldmx4(pa_l[mt], smb + PL_OFF + ao);
            }
            const int krow = ks * 16 + arow;
            #pragma unroll
            for (int nt = 0; nt < 2; nt++) {
                const uint32_t bo = SWZ128((uint32_t)(krow * 128
                                           + (wn2v + nt * 8) * 2));
                ldmx2t(vh_[nt], smb + KVH_OFF + bo);
                ldmx2t(vl_[nt], smb + KVL_OFF + bo);
            }
            #pragma unroll
            for (int mt = 0; mt < 2; mt++)
                #pragma unroll
                for (int nt = 0; nt < 2; nt++) {
                    mma_bf16(oacc[mt][nt], pa_h[mt], vh_[nt]);
                    mma_bf16(oacc[mt][nt], pa_h[mt], vl_[nt]);
                    mma_bf16(oacc[mt][nt], pa_l[mt], vh_[nt]);
                }
        }
    }

    // ---- epilogue: stage O, then convert to fp16 gAh (hi only) ----
    __syncthreads();
    float* stage = (float*)(sm + PH_OFF);   // [64][68]
    #pragma unroll
    for (int mt = 0; mt < 2; mt++)
        #pragma unroll
        for (int nt = 0; nt < 2; nt++) {
            const int r = wm2 + mt * 16 + (lane >> 2);
            const int c = wn2v + nt * 8 + 2 * (lane & 3);
            *(float2*)&stage[r * 68 + c] = make_float2(oacc[mt][nt][0], oacc[mt][nt][1]);
            *(float2*)&stage[(r + 8) * 68 + c] = make_float2(oacc[mt][nt][2], oacc[mt][nt][3]);
        }
    __syncthreads();
    {
        const int row = tid >> 2, q4 = tid & 3;
        const size_t base = ((size_t)(b * S_ + t0 + row)) * HID_ + h * 64 + q4 * 16;
        const float* sp = &stage[row * 68 + q4 * 16];
        __half2 hbuf[8];
        #pragma unroll
        for (int e = 0; e < 8; e++)
            hbuf[e] = __floats2half2_rn(sp[2 * e], sp[2 * e + 1]);
        *(int4*)(gAh + base)     = *(int4*)&hbuf[0];
        *(int4*)(gAh + base + 8) = *(int4*)&hbuf[4];
    }
}

// ---------------------------------------------------------------------------
extern "C" void kernel_launch(void* const* d_in, const int* in_sizes, int n_in,
                              void* d_out, int out_size) {
    const float* hidden = (const float*)d_in[0];
    const float* Wq     = (const float*)d_in[1];
    const float* Wo     = (const float*)d_in[2];
    float* out = (float*)d_out;
    (void)in_sizes; (void)n_in; (void)out_size;

    cudaFuncSetAttribute(gemm_mma<0>,
                         cudaFuncAttributeMaxDynamicSharedMemorySize, GT_SMEM);
    cudaFuncSetAttribute(gemm_mma<1>,
                         cudaFuncAttributeMaxDynamicSharedMemorySize, GT_SMEM);
    cudaFuncSetAttribute(attn_mma,
                         cudaFuncAttributeMaxDynamicSharedMemorySize, AT_SMEM);

    split_f16<0><<<(M_ * HID_ / 4 + 255) / 256, 256>>>(hidden, M_ * HID_);
    split_f16<1><<<(HID_ * HID_ / 4 + 255) / 256, 256>>>(Wq, HID_ * HID_);
    split_f16<2><<<(HID_ * HID_ / 4 + 255) / 256, 256>>>(Wo, HID_ * HID_);

    dim3 gemm_grid(HID_ / 128, M_ / 128);
    gemm_mma<0><<<gemm_grid, 256, GT_SMEM>>>(nullptr);

    dim3 attn_grid(S_ / 64, B_ * NH_);
    attn_mma<<<attn_grid, 256, AT_SMEM>>>();   // writes fp16 gAh for gemm<1>

    gemm_mma<1><<<gemm_grid, 256, GT_SMEM>>>(out);
}